// round 4
// baseline (speedup 1.0000x reference)
#include <cuda_runtime.h>
#include <math.h>

// Problem constants (fixed shapes from reference)
#define HID    2048
#define BATCH  2
#define SEQ    2048
#define NHEADS 16
#define HD     128
#define MROWS  (BATCH * SEQ)   // 4096

// ---------------------------------------------------------------------------
// Scratch (static __device__ arrays — no allocation anywhere)
// ---------------------------------------------------------------------------
__device__ float g_Q[(size_t)MROWS * HID];
__device__ float g_K[(size_t)MROWS * HID];
__device__ float g_V[(size_t)MROWS * HID];
__device__ float g_CTX[(size_t)MROWS * HID];

// ---------------------------------------------------------------------------
// Tiled SGEMM body: C[M,N] = A[M,K] @ W[K,N] + bias[N]
// M = 4096, N = K = 2048 (all hardcoded, dims divide tiles exactly).
// BM=BN=128, BK=8, 256 threads, 8x8 microtile per thread.
// ---------------------------------------------------------------------------
__device__ __forceinline__ void sgemm_body(const float* __restrict__ A,
                                           const float* __restrict__ W,
                                           const float* __restrict__ bias,
                                           float* __restrict__ C)
{
    __shared__ float As[8][128];
    __shared__ float Bs[8][128];

    const int tid  = threadIdx.x;
    const int row0 = blockIdx.y * 128;
    const int col0 = blockIdx.x * 128;

    // A loader: 128 rows x 8 cols, one float4 per thread (along K)
    const int arow = tid >> 1;
    const int acol = (tid & 1) * 4;
    // B loader: 8 rows x 128 cols, one float4 per thread (along N, coalesced)
    const int brow = tid >> 5;
    const int bcol = (tid & 31) * 4;

    const float* Ap = A + (size_t)(row0 + arow) * HID + acol;
    const float* Wp = W + (size_t)brow * HID + col0 + bcol;

    const int ty = tid >> 4;   // 0..15
    const int tx = tid & 15;   // 0..15

    float acc[8][8];
#pragma unroll
    for (int i = 0; i < 8; i++)
#pragma unroll
        for (int j = 0; j < 8; j++) acc[i][j] = 0.f;

    for (int kt = 0; kt < HID; kt += 8) {
        float4 av = *(const float4*)(Ap + kt);
        As[acol + 0][arow] = av.x;
        As[acol + 1][arow] = av.y;
        As[acol + 2][arow] = av.z;
        As[acol + 3][arow] = av.w;
        *(float4*)(&Bs[brow][bcol]) = *(const float4*)(Wp + (size_t)kt * HID);
        __syncthreads();

#pragma unroll
        for (int k = 0; k < 8; k++) {
            float a[8], b[8];
            *(float4*)(a)     = *(const float4*)(&As[k][ty * 8]);
            *(float4*)(a + 4) = *(const float4*)(&As[k][ty * 8 + 4]);
            *(float4*)(b)     = *(const float4*)(&Bs[k][tx * 8]);
            *(float4*)(b + 4) = *(const float4*)(&Bs[k][tx * 8 + 4]);
#pragma unroll
            for (int i = 0; i < 8; i++)
#pragma unroll
                for (int j = 0; j < 8; j++)
                    acc[i][j] = fmaf(a[i], b[j], acc[i][j]);
        }
        __syncthreads();
    }

    float bv[8];
#pragma unroll
    for (int j = 0; j < 8; j++) bv[j] = bias[col0 + tx * 8 + j];

#pragma unroll
    for (int i = 0; i < 8; i++) {
        float* Cp = C + (size_t)(row0 + ty * 8 + i) * HID + col0 + tx * 8;
        float4 v0 = make_float4(acc[i][0] + bv[0], acc[i][1] + bv[1],
                                acc[i][2] + bv[2], acc[i][3] + bv[3]);
        float4 v1 = make_float4(acc[i][4] + bv[4], acc[i][5] + bv[5],
                                acc[i][6] + bv[6], acc[i][7] + bv[7]);
        *(float4*)(Cp)     = v0;
        *(float4*)(Cp + 4) = v1;
    }
}

// QKV projections: gridDim.z selects (Wq->g_Q), (Wk->g_K), (Wv->g_V)
__global__ __launch_bounds__(256, 2)
void qkv_gemm_kernel(const float* __restrict__ X,
                     const float* __restrict__ Wq, const float* __restrict__ bq,
                     const float* __restrict__ Wk, const float* __restrict__ bk,
                     const float* __restrict__ Wv, const float* __restrict__ bv)
{
    const float* W;
    const float* bias;
    float* C;
    if (blockIdx.z == 0)      { W = Wq; bias = bq; C = g_Q; }
    else if (blockIdx.z == 1) { W = Wk; bias = bk; C = g_K; }
    else                      { W = Wv; bias = bv; C = g_V; }
    sgemm_body(X, W, bias, C);
}

// Output projection: out = g_CTX @ Wo + bo
__global__ __launch_bounds__(256, 2)
void out_gemm_kernel(const float* __restrict__ Wo, const float* __restrict__ bo,
                     float* __restrict__ out)
{
    sgemm_body(g_CTX, Wo, bo, out);
}

// ---------------------------------------------------------------------------
// Flash-style attention. One block = one (b,h) and 64 query rows.
// BM = BN = 64, D = 128, 256 threads, online softmax.
// Writes directly into the reference's permuted context layout:
//   ctx[b][d*16 + s/128][(s%128)*16 + h] = O[b,h,s,d]
// ---------------------------------------------------------------------------
#define ATTN_SMEM_FLOATS (3 * 64 * 128 + 64 * 65 + 3 * 64)
#define ATTN_SMEM_BYTES  (ATTN_SMEM_FLOATS * 4)

__global__ __launch_bounds__(256)
void attn_kernel()
{
    extern __shared__ float sm[];
    float* Qs  = sm;                 // 64 x 128
    float* Ks  = Qs + 64 * 128;      // 64 x 128
    float* Vs  = Ks + 64 * 128;      // 64 x 128
    float* Ss  = Vs + 64 * 128;      // 64 x 65 (padded)
    float* m_s = Ss + 64 * 65;       // 64
    float* l_s = m_s + 64;           // 64
    float* a_s = l_s + 64;           // 64

    const int tid = threadIdx.x;
    const int bh  = blockIdx.y;
    const int b   = bh >> 4;
    const int h   = bh & 15;
    const int q0  = blockIdx.x * 64;
    const size_t rowbase = (size_t)b * SEQ;
    const float scale = 0.08838834764831845f;  // 1/sqrt(128)

    // Load Q tile (64 x 128) once
    {
        const float* Qg = g_Q + (rowbase + q0) * HID + h * HD;
#pragma unroll
        for (int it = 0; it < 8; it++) {
            int idx = tid + it * 256;         // 0..2047 float4s
            int r   = idx >> 5;
            int dq  = (idx & 31) << 2;
            *(float4*)(Qs + r * 128 + dq) =
                *(const float4*)(Qg + (size_t)r * HID + dq);
        }
    }
    if (tid < 64) { m_s[tid] = -INFINITY; l_s[tid] = 0.f; }

    const int ty = tid >> 4;   // 0..15
    const int tx = tid & 15;   // 0..15

    float acc[4][8];
#pragma unroll
    for (int i = 0; i < 4; i++)
#pragma unroll
        for (int j = 0; j < 8; j++) acc[i][j] = 0.f;

    for (int jt = 0; jt < SEQ / 64; jt++) {
        __syncthreads();  // prior-iter readers of Ks/Vs/Ss done; also covers Q load on iter 0

        // Load K and V tiles (64 x 128 each)
        {
            const float* Kg = g_K + (rowbase + jt * 64) * HID + h * HD;
            const float* Vg = g_V + (rowbase + jt * 64) * HID + h * HD;
#pragma unroll
            for (int it = 0; it < 8; it++) {
                int idx = tid + it * 256;
                int r   = idx >> 5;
                int dq  = (idx & 31) << 2;
                *(float4*)(Ks + r * 128 + dq) =
                    *(const float4*)(Kg + (size_t)r * HID + dq);
                *(float4*)(Vs + r * 128 + dq) =
                    *(const float4*)(Vg + (size_t)r * HID + dq);
            }
        }
        __syncthreads();

        // S = (Q K^T) * scale : 64x64, each thread a 4x4 microtile
        {
            const int r0 = ty * 4;
            const int c0 = tx * 4;
            float s[4][4];
#pragma unroll
            for (int i = 0; i < 4; i++)
#pragma unroll
                for (int j = 0; j < 4; j++) s[i][j] = 0.f;

#pragma unroll 4
            for (int d4 = 0; d4 < 32; d4++) {
                float4 q[4], k4[4];
#pragma unroll
                for (int i = 0; i < 4; i++)
                    q[i] = *(const float4*)(Qs + (r0 + i) * 128 + d4 * 4);
#pragma unroll
                for (int j = 0; j < 4; j++)
                    k4[j] = *(const float4*)(Ks + (c0 + j) * 128 + d4 * 4);
#pragma unroll
                for (int i = 0; i < 4; i++)
#pragma unroll
                    for (int j = 0; j < 4; j++) {
                        s[i][j] = fmaf(q[i].x, k4[j].x, s[i][j]);
                        s[i][j] = fmaf(q[i].y, k4[j].y, s[i][j]);
                        s[i][j] = fmaf(q[i].z, k4[j].z, s[i][j]);
                        s[i][j] = fmaf(q[i].w, k4[j].w, s[i][j]);
                    }
            }
#pragma unroll
            for (int i = 0; i < 4; i++)
#pragma unroll
                for (int j = 0; j < 4; j++)
                    Ss[(r0 + i) * 65 + (c0 + j)] = s[i][j] * scale;
        }
        __syncthreads();

        // Online softmax row update (64 rows, one thread each)
        if (tid < 64) {
            const int r = tid;
            float mold = m_s[r];
            float mnew = mold;
#pragma unroll 8
            for (int c = 0; c < 64; c++)
                mnew = fmaxf(mnew, Ss[r * 65 + c]);
            float alpha = __expf(mold - mnew);   // exp(-inf)=0 on first tile
            float lsum  = l_s[r] * alpha;
#pragma unroll 8
            for (int c = 0; c < 64; c++) {
                float p = __expf(Ss[r * 65 + c] - mnew);
                Ss[r * 65 + c] = p;
                lsum += p;
            }
            m_s[r] = mnew;
            l_s[r] = lsum;
            a_s[r] = alpha;
        }
        __syncthreads();

        // O update: acc = acc*alpha + P @ V  (each thread: 4 rows x 8 cols)
        {
            const int r0 = ty * 4;
            const int c0 = tx * 8;
#pragma unroll
            for (int i = 0; i < 4; i++) {
                float al = a_s[r0 + i];
#pragma unroll
                for (int j = 0; j < 8; j++) acc[i][j] *= al;
            }
#pragma unroll 4
            for (int c = 0; c < 64; c++) {
                float4 v0 = *(const float4*)(Vs + c * 128 + c0);
                float4 v1 = *(const float4*)(Vs + c * 128 + c0 + 4);
#pragma unroll
                for (int i = 0; i < 4; i++) {
                    float p = Ss[(r0 + i) * 65 + c];
                    acc[i][0] = fmaf(p, v0.x, acc[i][0]);
                    acc[i][1] = fmaf(p, v0.y, acc[i][1]);
                    acc[i][2] = fmaf(p, v0.z, acc[i][2]);
                    acc[i][3] = fmaf(p, v0.w, acc[i][3]);
                    acc[i][4] = fmaf(p, v1.x, acc[i][4]);
                    acc[i][5] = fmaf(p, v1.y, acc[i][5]);
                    acc[i][6] = fmaf(p, v1.z, acc[i][6]);
                    acc[i][7] = fmaf(p, v1.w, acc[i][7]);
                }
            }
        }
    }

    // Normalize and scatter into the reference's permuted context layout.
    // ctx row = d*16 + s/128, col = (s%128)*16 + h
    {
        const int r0 = ty * 4;
        const int c0 = tx * 8;
#pragma unroll
        for (int i = 0; i < 4; i++) {
            int   s_g     = q0 + r0 + i;
            float inv     = 1.f / l_s[r0 + i];
            int   srow_hi = s_g >> 7;     // s / 128
            int   srow_lo = s_g & 127;    // s % 128
#pragma unroll
            for (int j = 0; j < 8; j++) {
                int d = c0 + j;
                size_t off = (size_t)b * ((size_t)SEQ * HID)
                           + (size_t)(d * NHEADS + srow_hi) * HID
                           + (size_t)srow_lo * NHEADS + h;
                g_CTX[off] = acc[i][j] * inv;
            }
        }
    }
}

// ---------------------------------------------------------------------------
// Launch: 3 kernels, all graph-capturable (launches only).
// ---------------------------------------------------------------------------
extern "C" void kernel_launch(void* const* d_in, const int* in_sizes, int n_in,
                              void* d_out, int out_size)
{
    (void)in_sizes; (void)n_in; (void)out_size;
    const float* X  = (const float*)d_in[0];
    const float* Wq = (const float*)d_in[1];
    const float* bq = (const float*)d_in[2];
    const float* Wk = (const float*)d_in[3];
    const float* bk = (const float*)d_in[4];
    const float* Wv = (const float*)d_in[5];
    const float* bv = (const float*)d_in[6];
    const float* Wo = (const float*)d_in[7];
    const float* bo = (const float*)d_in[8];
    float* out = (float*)d_out;

    // Fused QKV projections (z selects which weight/output)
    dim3 gq(HID / 128, MROWS / 128, 3);
    qkv_gemm_kernel<<<gq, 256>>>(X, Wq, bq, Wk, bk, Wv, bv);

    // Flash attention -> permuted context
    cudaFuncSetAttribute(attn_kernel,
                         cudaFuncAttributeMaxDynamicSharedMemorySize,
                         ATTN_SMEM_BYTES);
    dim3 ga(SEQ / 64, BATCH * NHEADS);
    attn_kernel<<<ga, 256, ATTN_SMEM_BYTES>>>();

    // Output projection
    dim3 go(HID / 128, MROWS / 128, 1);
    out_gemm_kernel<<<go, 256>>>(Wo, bo, out);
}

// round 6
// speedup vs baseline: 1.1491x; 1.1491x over previous
#include <cuda_runtime.h>
#include <math.h>
#include <stdint.h>

// Problem constants
#define HID    2048
#define BATCH  2
#define SEQ    2048
#define NHEADS 16
#define HD     128
#define MROWS  (BATCH * SEQ)   // 4096

// ---------------------------------------------------------------------------
// Scratch (static __device__ arrays — no allocation anywhere)
// ---------------------------------------------------------------------------
__device__ float g_Q[(size_t)MROWS * HID];
__device__ float g_K[(size_t)MROWS * HID];
__device__ float g_V[(size_t)MROWS * HID];
__device__ float g_CTX[(size_t)MROWS * HID];

// ---------------------------------------------------------------------------
// Helpers
// ---------------------------------------------------------------------------
__device__ __forceinline__ float f2tf32f(float f) {
    uint32_t r;
    asm("cvt.rna.tf32.f32 %0, %1;" : "=r"(r) : "f"(f));
    return __uint_as_float(r);
}

__device__ __forceinline__ void mma_tf32(float& d0, float& d1, float& d2, float& d3,
                                         float a0, float a1, float a2, float a3,
                                         float b0, float b1)
{
    asm volatile(
        "mma.sync.aligned.m16n8k8.row.col.f32.tf32.tf32.f32 "
        "{%0,%1,%2,%3}, {%4,%5,%6,%7}, {%8,%9}, {%0,%1,%2,%3};"
        : "+f"(d0), "+f"(d1), "+f"(d2), "+f"(d3)
        : "r"(__float_as_uint(a0)), "r"(__float_as_uint(a1)),
          "r"(__float_as_uint(a2)), "r"(__float_as_uint(a3)),
          "r"(__float_as_uint(b0)), "r"(__float_as_uint(b1)));
}

// ---------------------------------------------------------------------------
// tf32 mma.sync GEMM: C[4096,2048] = A[4096,2048] @ W[2048,2048] + bias
// CTA tile 128x128, BK=32, 8 warps (2 M x 4 N), warp tile 64x32.
// Smem layout per operand tile: 128 rows x 32 floats, K-permuted
//   p(k) = (k%4)*8 + k/4, chunk-XOR swizzled: chunk_phys = chunk ^ (row&7).
// This makes every thread's fragment data for all 4 k-steps contiguous
// (two float4 per row), so all fragment loads are LDS.128.
// ---------------------------------------------------------------------------
#define GEMM_SMEM_BYTES (2 * 2 * 4096 * 4)   // 2 ops x 2 stages x 4096 floats

__device__ __forceinline__ void tf32_gemm_body(const float* __restrict__ A,
                                               const float* __restrict__ W,
                                               const float* __restrict__ bias,
                                               float* __restrict__ C)
{
    extern __shared__ float sm[];
    float* smA = sm;           // [2][4096]
    float* smB = sm + 8192;    // [2][4096]

    const int tid   = threadIdx.x;
    const int lane  = tid & 31;
    const int wid   = tid >> 5;
    const int warpM = wid >> 2;      // 0..1
    const int warpN = wid & 3;       // 0..3
    const int csel  = lane & 3;      // k-mod-4 selector
    const int g     = lane >> 2;     // group id 0..7

    const int m0 = blockIdx.y * 128;
    const int n0 = blockIdx.x * 128;

    const float* Abase = A + (size_t)m0 * HID;
    const float* Wbase = W + n0;

    // Loader coords
    const int ar = tid >> 1;                 // not used; see below
    (void)ar;

    float4 stA[4], stB[4];

    // ---- global load of chunk kt into staging regs ----
    auto ldg_chunk = [&](int kt) {
        const float* Ag = Abase + kt * 32;
#pragma unroll
        for (int i = 0; i < 4; i++) {
            int idx = tid + i * 256;          // 0..1023
            int r = idx >> 3;                 // row 0..127
            int j = idx & 7;                  // float4 along k
            stA[i] = *(const float4*)(Ag + (size_t)r * HID + j * 4);
        }
        const float* Wg = Wbase + (size_t)(kt * 32) * HID;
#pragma unroll
        for (int i = 0; i < 4; i++) {
            int idx = tid + i * 256;
            int k  = idx >> 5;                // 0..31
            int jn = idx & 31;                // float4 along n
            stB[i] = *(const float4*)(Wg + (size_t)k * HID + jn * 4);
        }
    };

    // ---- store staging regs into smem stage s (with tf32 cvt + permute) ----
    auto sts_chunk = [&](int s) {
        float* a = smA + s * 4096;
        float* b = smB + s * 4096;
#pragma unroll
        for (int i = 0; i < 4; i++) {
            int idx = tid + i * 256;
            int r = idx >> 3;
            int j = idx & 7;
            const float v[4] = { stA[i].x, stA[i].y, stA[i].z, stA[i].w };
#pragma unroll
            for (int e = 0; e < 4; e++) {
                int p     = e * 8 + j;                  // permuted position
                int chunk = (p >> 2) ^ (r & 7);
                a[r * 32 + chunk * 4 + (p & 3)] = f2tf32f(v[e]);
            }
        }
#pragma unroll
        for (int i = 0; i < 4; i++) {
            int idx = tid + i * 256;
            int k  = idx >> 5;
            int jn = idx & 31;
            int p     = (k & 3) * 8 + (k >> 2);
            int chunk0 = p >> 2;
            int off    = p & 3;
            const float v[4] = { stB[i].x, stB[i].y, stB[i].z, stB[i].w };
#pragma unroll
            for (int e = 0; e < 4; e++) {
                int n = jn * 4 + e;
                b[n * 32 + ((chunk0 ^ (n & 7)) * 4) + off] = f2tf32f(v[e]);
            }
        }
    };

    float acc[4][4][4];
#pragma unroll
    for (int mt = 0; mt < 4; mt++)
#pragma unroll
        for (int nt = 0; nt < 4; nt++)
#pragma unroll
            for (int e = 0; e < 4; e++) acc[mt][nt][e] = 0.f;

    // ---- compute one chunk from smem stage s ----
    auto compute = [&](int s) {
        const float* a = smA + s * 4096;
        const float* b = smB + s * 4096;
#pragma unroll
        for (int half = 0; half < 2; half++) {
            const int q = 2 * csel + half;     // logical chunk for this thread
            float4 A0[4], A8[4], Bf[4];
#pragma unroll
            for (int mt = 0; mt < 4; mt++) {
                int r0 = warpM * 64 + mt * 16 + g;
                int r8 = r0 + 8;
                A0[mt] = *(const float4*)(a + r0 * 32 + ((q ^ (r0 & 7)) * 4));
                A8[mt] = *(const float4*)(a + r8 * 32 + ((q ^ (r8 & 7)) * 4));
            }
#pragma unroll
            for (int nt = 0; nt < 4; nt++) {
                int n = warpN * 32 + nt * 8 + g;
                Bf[nt] = *(const float4*)(b + n * 32 + ((q ^ (n & 7)) * 4));
            }
#pragma unroll
            for (int mt = 0; mt < 4; mt++)
#pragma unroll
                for (int nt = 0; nt < 4; nt++) {
                    mma_tf32(acc[mt][nt][0], acc[mt][nt][1],
                             acc[mt][nt][2], acc[mt][nt][3],
                             A0[mt].x, A8[mt].x, A0[mt].y, A8[mt].y,
                             Bf[nt].x, Bf[nt].y);
                    mma_tf32(acc[mt][nt][0], acc[mt][nt][1],
                             acc[mt][nt][2], acc[mt][nt][3],
                             A0[mt].z, A8[mt].z, A0[mt].w, A8[mt].w,
                             Bf[nt].z, Bf[nt].w);
                }
        }
    };

    // ---- pipeline ----
    ldg_chunk(0);
    sts_chunk(0);
    __syncthreads();

    for (int c = 0; c < HID / 32; c++) {       // 64 chunks
        const int s = c & 1;
        if (c < HID / 32 - 1) ldg_chunk(c + 1);
        compute(s);
        if (c < HID / 32 - 1) {
            sts_chunk(s ^ 1);
            __syncthreads();
        }
    }

    // ---- epilogue: bias + store ----
#pragma unroll
    for (int mt = 0; mt < 4; mt++) {
        int row = m0 + warpM * 64 + mt * 16 + g;
#pragma unroll
        for (int nt = 0; nt < 4; nt++) {
            int col = n0 + warpN * 32 + nt * 8 + 2 * csel;
            float b0 = __ldg(bias + col);
            float b1 = __ldg(bias + col + 1);
            float2 lo = make_float2(acc[mt][nt][0] + b0, acc[mt][nt][1] + b1);
            float2 hi = make_float2(acc[mt][nt][2] + b0, acc[mt][nt][3] + b1);
            *(float2*)(C + (size_t)row * HID + col)       = lo;
            *(float2*)(C + (size_t)(row + 8) * HID + col) = hi;
        }
    }
}

// QKV projections: gridDim.z selects output
__global__ __launch_bounds__(256)
void qkv_gemm_tc(const float* __restrict__ X,
                 const float* __restrict__ Wq, const float* __restrict__ bq,
                 const float* __restrict__ Wk, const float* __restrict__ bk,
                 const float* __restrict__ Wv, const float* __restrict__ bv)
{
    const float* W; const float* b; float* Cp;
    if (blockIdx.z == 0)      { W = Wq; b = bq; Cp = g_Q; }
    else if (blockIdx.z == 1) { W = Wk; b = bk; Cp = g_K; }
    else                      { W = Wv; b = bv; Cp = g_V; }
    tf32_gemm_body(X, W, b, Cp);
}

__global__ __launch_bounds__(256)
void out_gemm_tc(const float* __restrict__ Wo, const float* __restrict__ bo,
                 float* __restrict__ out)
{
    tf32_gemm_body(g_CTX, Wo, bo, out);
}

// ---------------------------------------------------------------------------
// Flash-style attention (proven correct in R4 bench).
// One block = one (b,h) and 64 query rows. Writes permuted context layout:
//   ctx[b][d*16 + s/128][(s%128)*16 + h] = O[b,h,s,d]
// ---------------------------------------------------------------------------
#define ATTN_SMEM_FLOATS (3 * 64 * 128 + 64 * 65 + 3 * 64)
#define ATTN_SMEM_BYTES  (ATTN_SMEM_FLOATS * 4)

__global__ __launch_bounds__(256)
void attn_kernel()
{
    extern __shared__ float smf[];
    float* Qs  = smf;
    float* Ks  = Qs + 64 * 128;
    float* Vs  = Ks + 64 * 128;
    float* Ss  = Vs + 64 * 128;
    float* m_s = Ss + 64 * 65;
    float* l_s = m_s + 64;
    float* a_s = l_s + 64;

    const int tid = threadIdx.x;
    const int bh  = blockIdx.y;
    const int b   = bh >> 4;
    const int h   = bh & 15;
    const int q0  = blockIdx.x * 64;
    const size_t rowbase = (size_t)b * SEQ;
    const float scale = 0.08838834764831845f;

    {
        const float* Qg = g_Q + (rowbase + q0) * HID + h * HD;
#pragma unroll
        for (int it = 0; it < 8; it++) {
            int idx = tid + it * 256;
            int r   = idx >> 5;
            int dq  = (idx & 31) << 2;
            *(float4*)(Qs + r * 128 + dq) =
                *(const float4*)(Qg + (size_t)r * HID + dq);
        }
    }
    if (tid < 64) { m_s[tid] = -INFINITY; l_s[tid] = 0.f; }

    const int ty = tid >> 4;
    const int tx = tid & 15;

    float acc[4][8];
#pragma unroll
    for (int i = 0; i < 4; i++)
#pragma unroll
        for (int j = 0; j < 8; j++) acc[i][j] = 0.f;

    for (int jt = 0; jt < SEQ / 64; jt++) {
        __syncthreads();
        {
            const float* Kg = g_K + (rowbase + jt * 64) * HID + h * HD;
            const float* Vg = g_V + (rowbase + jt * 64) * HID + h * HD;
#pragma unroll
            for (int it = 0; it < 8; it++) {
                int idx = tid + it * 256;
                int r   = idx >> 5;
                int dq  = (idx & 31) << 2;
                *(float4*)(Ks + r * 128 + dq) =
                    *(const float4*)(Kg + (size_t)r * HID + dq);
                *(float4*)(Vs + r * 128 + dq) =
                    *(const float4*)(Vg + (size_t)r * HID + dq);
            }
        }
        __syncthreads();

        {
            const int r0 = ty * 4;
            const int c0 = tx * 4;
            float s[4][4];
#pragma unroll
            for (int i = 0; i < 4; i++)
#pragma unroll
                for (int j = 0; j < 4; j++) s[i][j] = 0.f;

#pragma unroll 4
            for (int d4 = 0; d4 < 32; d4++) {
                float4 q[4], k4[4];
#pragma unroll
                for (int i = 0; i < 4; i++)
                    q[i] = *(const float4*)(Qs + (r0 + i) * 128 + d4 * 4);
#pragma unroll
                for (int j = 0; j < 4; j++)
                    k4[j] = *(const float4*)(Ks + (c0 + j) * 128 + d4 * 4);
#pragma unroll
                for (int i = 0; i < 4; i++)
#pragma unroll
                    for (int j = 0; j < 4; j++) {
                        s[i][j] = fmaf(q[i].x, k4[j].x, s[i][j]);
                        s[i][j] = fmaf(q[i].y, k4[j].y, s[i][j]);
                        s[i][j] = fmaf(q[i].z, k4[j].z, s[i][j]);
                        s[i][j] = fmaf(q[i].w, k4[j].w, s[i][j]);
                    }
            }
#pragma unroll
            for (int i = 0; i < 4; i++)
#pragma unroll
                for (int j = 0; j < 4; j++)
                    Ss[(r0 + i) * 65 + (c0 + j)] = s[i][j] * scale;
        }
        __syncthreads();

        if (tid < 64) {
            const int r = tid;
            float mold = m_s[r];
            float mnew = mold;
#pragma unroll 8
            for (int c = 0; c < 64; c++)
                mnew = fmaxf(mnew, Ss[r * 65 + c]);
            float alpha = __expf(mold - mnew);
            float lsum  = l_s[r] * alpha;
#pragma unroll 8
            for (int c = 0; c < 64; c++) {
                float p = __expf(Ss[r * 65 + c] - mnew);
                Ss[r * 65 + c] = p;
                lsum += p;
            }
            m_s[r] = mnew;
            l_s[r] = lsum;
            a_s[r] = alpha;
        }
        __syncthreads();

        {
            const int r0 = ty * 4;
            const int c0 = tx * 8;
#pragma unroll
            for (int i = 0; i < 4; i++) {
                float al = a_s[r0 + i];
#pragma unroll
                for (int j = 0; j < 8; j++) acc[i][j] *= al;
            }
#pragma unroll 4
            for (int c = 0; c < 64; c++) {
                float4 v0 = *(const float4*)(Vs + c * 128 + c0);
                float4 v1 = *(const float4*)(Vs + c * 128 + c0 + 4);
#pragma unroll
                for (int i = 0; i < 4; i++) {
                    float p = Ss[(r0 + i) * 65 + c];
                    acc[i][0] = fmaf(p, v0.x, acc[i][0]);
                    acc[i][1] = fmaf(p, v0.y, acc[i][1]);
                    acc[i][2] = fmaf(p, v0.z, acc[i][2]);
                    acc[i][3] = fmaf(p, v0.w, acc[i][3]);
                    acc[i][4] = fmaf(p, v1.x, acc[i][4]);
                    acc[i][5] = fmaf(p, v1.y, acc[i][5]);
                    acc[i][6] = fmaf(p, v1.z, acc[i][6]);
                    acc[i][7] = fmaf(p, v1.w, acc[i][7]);
                }
            }
        }
    }

    {
        const int r0 = ty * 4;
        const int c0 = tx * 8;
#pragma unroll
        for (int i = 0; i < 4; i++) {
            int   s_g     = q0 + r0 + i;
            float inv     = 1.f / l_s[r0 + i];
            int   srow_hi = s_g >> 7;
            int   srow_lo = s_g & 127;
#pragma unroll
            for (int j = 0; j < 8; j++) {
                int d = c0 + j;
                size_t off = (size_t)b * ((size_t)SEQ * HID)
                           + (size_t)(d * NHEADS + srow_hi) * HID
                           + (size_t)srow_lo * NHEADS + h;
                g_CTX[off] = acc[i][j] * inv;
            }
        }
    }
}

// ---------------------------------------------------------------------------
// Launch
// ---------------------------------------------------------------------------
extern "C" void kernel_launch(void* const* d_in, const int* in_sizes, int n_in,
                              void* d_out, int out_size)
{
    (void)in_sizes; (void)n_in; (void)out_size;
    const float* X  = (const float*)d_in[0];
    const float* Wq = (const float*)d_in[1];
    const float* bq = (const float*)d_in[2];
    const float* Wk = (const float*)d_in[3];
    const float* bk = (const float*)d_in[4];
    const float* Wv = (const float*)d_in[5];
    const float* bv = (const float*)d_in[6];
    const float* Wo = (const float*)d_in[7];
    const float* bo = (const float*)d_in[8];
    float* out = (float*)d_out;

    cudaFuncSetAttribute(qkv_gemm_tc, cudaFuncAttributeMaxDynamicSharedMemorySize,
                         GEMM_SMEM_BYTES);
    cudaFuncSetAttribute(out_gemm_tc, cudaFuncAttributeMaxDynamicSharedMemorySize,
                         GEMM_SMEM_BYTES);
    cudaFuncSetAttribute(attn_kernel, cudaFuncAttributeMaxDynamicSharedMemorySize,
                         ATTN_SMEM_BYTES);

    dim3 gq(HID / 128, MROWS / 128, 3);
    qkv_gemm_tc<<<gq, 256, GEMM_SMEM_BYTES>>>(X, Wq, bq, Wk, bk, Wv, bv);

    dim3 ga(SEQ / 64, BATCH * NHEADS);
    attn_kernel<<<ga, 256, ATTN_SMEM_BYTES>>>();

    dim3 go(HID / 128, MROWS / 128, 1);
    out_gemm_tc<<<go, 256, GEMM_SMEM_BYTES>>>(Wo, bo, out);
}

// round 7
// speedup vs baseline: 2.8168x; 2.4514x over previous
#include <cuda_runtime.h>
#include <math.h>
#include <stdint.h>

// Problem constants
#define HID    2048
#define BATCH  2
#define SEQ    2048
#define NHEADS 16
#define HD     128
#define MROWS  (BATCH * SEQ)   // 4096

// ---------------------------------------------------------------------------
// Scratch (static __device__ arrays — no allocation anywhere)
// ---------------------------------------------------------------------------
__device__ float g_Q[(size_t)MROWS * HID];
__device__ float g_K[(size_t)MROWS * HID];
__device__ float g_V[(size_t)MROWS * HID];
__device__ float g_CTX[(size_t)MROWS * HID];

// ---------------------------------------------------------------------------
// Helpers
// ---------------------------------------------------------------------------
__device__ __forceinline__ float f2tf32f(float f) {
    uint32_t r;
    asm("cvt.rna.tf32.f32 %0, %1;" : "=r"(r) : "f"(f));
    return __uint_as_float(r);
}

__device__ __forceinline__ void mma_tf32(float& d0, float& d1, float& d2, float& d3,
                                         float a0, float a1, float a2, float a3,
                                         float b0, float b1)
{
    asm volatile(
        "mma.sync.aligned.m16n8k8.row.col.f32.tf32.tf32.f32 "
        "{%0,%1,%2,%3}, {%4,%5,%6,%7}, {%8,%9}, {%0,%1,%2,%3};"
        : "+f"(d0), "+f"(d1), "+f"(d2), "+f"(d3)
        : "r"(__float_as_uint(a0)), "r"(__float_as_uint(a1)),
          "r"(__float_as_uint(a2)), "r"(__float_as_uint(a3)),
          "r"(__float_as_uint(b0)), "r"(__float_as_uint(b1)));
}

// ---------------------------------------------------------------------------
// tf32 mma.sync GEMM: C[4096,2048] = A[4096,2048] @ W[2048,2048] + bias
// CTA 128x128, BK=32, 256 threads, 8 warps (2M x 4N), warp tile 64x32.
// A smem: permuted layout (proven R5): per row 32 floats, pos p(k)=(k%4)*8+k/4,
//   chunk-XOR swizzle -> conflict-free LDS.128 fragment loads.
// B smem: plain padded Bs[k][n], row stride 136 floats:
//   - STS: float4, bank = (8k + 4*lane) % 32 -> conflict-free
//   - frag: scalar LDS.32 at bank = (8*csel + g + const) % 32 -> conflict-free
// ---------------------------------------------------------------------------
#define BSTRIDE 136
#define GEMM_SMEM_FLOATS (2 * 4096 + 2 * (32 * BSTRIDE))
#define GEMM_SMEM_BYTES  (GEMM_SMEM_FLOATS * 4)

__device__ __forceinline__ void tf32_gemm_body(const float* __restrict__ A,
                                               const float* __restrict__ W,
                                               const float* __restrict__ bias,
                                               float* __restrict__ C)
{
    extern __shared__ float sm[];
    float* smA = sm;                    // 2 stages x 4096
    float* smB = sm + 8192;             // 2 stages x 4352

    const int tid   = threadIdx.x;
    const int lane  = tid & 31;
    const int wid   = tid >> 5;
    const int warpM = wid >> 2;      // 0..1
    const int warpN = wid & 3;       // 0..3
    const int csel  = lane & 3;
    const int g     = lane >> 2;

    const int m0 = blockIdx.y * 128;
    const int n0 = blockIdx.x * 128;

    const float* Abase = A + (size_t)m0 * HID;
    const float* Wbase = W + n0;

    float4 stA[4], stB[4];

    auto ldg_chunk = [&](int kt) {
        const float* Ag = Abase + kt * 32;
#pragma unroll
        for (int i = 0; i < 4; i++) {
            int idx = tid + i * 256;
            int r = idx >> 3;
            int j = idx & 7;
            stA[i] = *(const float4*)(Ag + (size_t)r * HID + j * 4);
        }
        const float* Wg = Wbase + (size_t)(kt * 32) * HID;
#pragma unroll
        for (int i = 0; i < 4; i++) {
            int idx = tid + i * 256;
            int k  = idx >> 5;
            int jn = idx & 31;
            stB[i] = *(const float4*)(Wg + (size_t)k * HID + jn * 4);
        }
    };

    auto sts_chunk = [&](int s) {
        float* a = smA + s * 4096;
        float* b = smB + s * (32 * BSTRIDE);
#pragma unroll
        for (int i = 0; i < 4; i++) {
            int idx = tid + i * 256;
            int r = idx >> 3;
            int j = idx & 7;
            const float v[4] = { stA[i].x, stA[i].y, stA[i].z, stA[i].w };
#pragma unroll
            for (int e = 0; e < 4; e++) {
                int p     = e * 8 + j;
                int chunk = (p >> 2) ^ (r & 7);
                a[r * 32 + chunk * 4 + (p & 3)] = f2tf32f(v[e]);
            }
        }
#pragma unroll
        for (int i = 0; i < 4; i++) {
            int idx = tid + i * 256;
            int k  = idx >> 5;
            int jn = idx & 31;
            float4 t;
            t.x = f2tf32f(stB[i].x);
            t.y = f2tf32f(stB[i].y);
            t.z = f2tf32f(stB[i].z);
            t.w = f2tf32f(stB[i].w);
            *(float4*)(b + k * BSTRIDE + jn * 4) = t;
        }
    };

    float acc[4][4][4];
#pragma unroll
    for (int mt = 0; mt < 4; mt++)
#pragma unroll
        for (int nt = 0; nt < 4; nt++)
#pragma unroll
            for (int e = 0; e < 4; e++) acc[mt][nt][e] = 0.f;

    auto compute = [&](int s) {
        const float* a = smA + s * 4096;
        const float* b = smB + s * (32 * BSTRIDE);
#pragma unroll
        for (int half = 0; half < 2; half++) {
            const int q = 2 * csel + half;
            float4 A0[4], A8[4];
#pragma unroll
            for (int mt = 0; mt < 4; mt++) {
                int r0 = warpM * 64 + mt * 16 + g;
                int r8 = r0 + 8;
                A0[mt] = *(const float4*)(a + r0 * 32 + ((q ^ (r0 & 7)) * 4));
                A8[mt] = *(const float4*)(a + r8 * 32 + ((q ^ (r8 & 7)) * 4));
            }
            const int kb = csel + 16 * half;
#pragma unroll
            for (int nt = 0; nt < 4; nt++) {
                int n = warpN * 32 + nt * 8 + g;
                const float* bp = b + n;
                float b0 = bp[(kb + 0)  * BSTRIDE];
                float b1 = bp[(kb + 4)  * BSTRIDE];
                float b2 = bp[(kb + 8)  * BSTRIDE];
                float b3 = bp[(kb + 12) * BSTRIDE];
#pragma unroll
                for (int mt = 0; mt < 4; mt++) {
                    mma_tf32(acc[mt][nt][0], acc[mt][nt][1],
                             acc[mt][nt][2], acc[mt][nt][3],
                             A0[mt].x, A8[mt].x, A0[mt].y, A8[mt].y, b0, b1);
                    mma_tf32(acc[mt][nt][0], acc[mt][nt][1],
                             acc[mt][nt][2], acc[mt][nt][3],
                             A0[mt].z, A8[mt].z, A0[mt].w, A8[mt].w, b2, b3);
                }
            }
        }
    };

    ldg_chunk(0);
    sts_chunk(0);
    __syncthreads();

    for (int c = 0; c < HID / 32; c++) {
        const int s = c & 1;
        if (c < HID / 32 - 1) ldg_chunk(c + 1);
        compute(s);
        if (c < HID / 32 - 1) {
            sts_chunk(s ^ 1);
            __syncthreads();
        }
    }

#pragma unroll
    for (int mt = 0; mt < 4; mt++) {
        int row = m0 + warpM * 64 + mt * 16 + g;
#pragma unroll
        for (int nt = 0; nt < 4; nt++) {
            int col = n0 + warpN * 32 + nt * 8 + 2 * csel;
            float b0 = __ldg(bias + col);
            float b1 = __ldg(bias + col + 1);
            float2 lo = make_float2(acc[mt][nt][0] + b0, acc[mt][nt][1] + b1);
            float2 hi = make_float2(acc[mt][nt][2] + b0, acc[mt][nt][3] + b1);
            *(float2*)(C + (size_t)row * HID + col)       = lo;
            *(float2*)(C + (size_t)(row + 8) * HID + col) = hi;
        }
    }
}

__global__ __launch_bounds__(256)
void qkv_gemm_tc(const float* __restrict__ X,
                 const float* __restrict__ Wq, const float* __restrict__ bq,
                 const float* __restrict__ Wk, const float* __restrict__ bk,
                 const float* __restrict__ Wv, const float* __restrict__ bv)
{
    const float* W; const float* b; float* Cp;
    if (blockIdx.z == 0)      { W = Wq; b = bq; Cp = g_Q; }
    else if (blockIdx.z == 1) { W = Wk; b = bk; Cp = g_K; }
    else                      { W = Wv; b = bv; Cp = g_V; }
    tf32_gemm_body(X, W, b, Cp);
}

__global__ __launch_bounds__(256)
void out_gemm_tc(const float* __restrict__ Wo, const float* __restrict__ bo,
                 float* __restrict__ out)
{
    tf32_gemm_body(g_CTX, Wo, bo, out);
}

// ---------------------------------------------------------------------------
// Attention v2: QK^T via tf32 mma (both operands in the proven permuted
// layout — Q and K tiles are both d(=k)-contiguous), softmax parallelized
// 4 threads/row, PV in fp32 with conflict-free padded V layout.
// One CTA = (b,h) x 64 query rows. Output scattered to the reference's
// permuted context layout: ctx[b][d*16 + s/128][(s%128)*16 + h].
// ---------------------------------------------------------------------------
#define SSTRIDE 66
#define VSTRIDE 132
// floats: Qs 8192 | Ks 8192 | Vs 64*132=8448 | Ss 64*66=4224 | m/l/a 192
#define ATTN_SMEM_FLOATS (8192 + 8192 + 8448 + 4224 + 192)
#define ATTN_SMEM_BYTES  (ATTN_SMEM_FLOATS * 4)

__global__ __launch_bounds__(256)
void attn_kernel()
{
    extern __shared__ float smf[];
    float* Qs  = smf;                    // 4 chunks x 64 x 32 (permuted tf32)
    float* Ks  = Qs + 8192;              // 4 chunks x 64 x 32 (permuted tf32)
    float* Vs  = Ks + 8192;              // 64 x VSTRIDE (fp32)
    float* Ss  = Vs + 8448;              // 64 x SSTRIDE (fp32)
    float* m_s = Ss + 64 * SSTRIDE;      // 64
    float* l_s = m_s + 64;               // 64
    float* a_s = l_s + 64;               // 64

    const int tid  = threadIdx.x;
    const int lane = tid & 31;
    const int wid  = tid >> 5;
    const int warpM = wid >> 1;      // 0..3  (16-row S slabs)
    const int warpN = wid & 1;       // 0..1  (32-col S slabs)
    const int csel  = lane & 3;
    const int g     = lane >> 2;

    const int bh  = blockIdx.y;
    const int b   = bh >> 4;
    const int h   = bh & 15;
    const int q0  = blockIdx.x * 64;
    const size_t rowbase = (size_t)b * SEQ;
    const float scale = 0.08838834764831845f;   // 1/sqrt(128)

    // PV thread mapping: 4 rows x (4 + 4) interleaved columns
    const int ty = tid >> 4;         // 0..15 -> rows 4*ty
    const int tx = tid & 15;         // cols 4*tx and 64+4*tx
    const int pr0 = ty * 4;
    const int cA  = 4 * tx;
    const int cB  = 64 + 4 * tx;

    // ---- load Q tile (64 x 128) into permuted tf32 layout ----
    {
        const float* Qg = g_Q + (rowbase + q0) * HID + h * HD;
#pragma unroll
        for (int it = 0; it < 8; it++) {
            int idx  = tid + it * 256;        // 0..2047 float4
            int ch   = idx >> 9;              // 0..3
            int idx2 = idx & 511;
            int r    = idx2 >> 3;             // 0..63
            int j    = idx2 & 7;
            float4 v = *(const float4*)(Qg + (size_t)r * HID + ch * 32 + j * 4);
            float* dst = Qs + ch * 2048;
            const float vv[4] = { v.x, v.y, v.z, v.w };
#pragma unroll
            for (int e = 0; e < 4; e++) {
                int p     = e * 8 + j;
                int chunk = (p >> 2) ^ (r & 7);
                dst[r * 32 + chunk * 4 + (p & 3)] = f2tf32f(vv[e]);
            }
        }
    }
    if (tid < 64) { m_s[tid] = -INFINITY; l_s[tid] = 0.f; }

    float accO[4][8];
#pragma unroll
    for (int i = 0; i < 4; i++)
#pragma unroll
        for (int j = 0; j < 8; j++) accO[i][j] = 0.f;

    for (int jt = 0; jt < SEQ / 64; jt++) {
        __syncthreads();   // prior-iter Vs/Ss/Ks readers done (covers Q load on it 0)

        // ---- load K tile (permuted tf32) + V tile (padded fp32) ----
        {
            const float* Kg = g_K + (rowbase + jt * 64) * HID + h * HD;
            const float* Vg = g_V + (rowbase + jt * 64) * HID + h * HD;
#pragma unroll
            for (int it = 0; it < 8; it++) {
                int idx  = tid + it * 256;
                int ch   = idx >> 9;
                int idx2 = idx & 511;
                int r    = idx2 >> 3;
                int j    = idx2 & 7;
                float4 v = *(const float4*)(Kg + (size_t)r * HID + ch * 32 + j * 4);
                float* dst = Ks + ch * 2048;
                const float vv[4] = { v.x, v.y, v.z, v.w };
#pragma unroll
                for (int e = 0; e < 4; e++) {
                    int p     = e * 8 + j;
                    int chunk = (p >> 2) ^ (r & 7);
                    dst[r * 32 + chunk * 4 + (p & 3)] = f2tf32f(vv[e]);
                }
                // V: rows via idx>>5 (const per warp), cols 4*lane
                int vr = idx >> 5;
                int vd = (idx & 31) * 4;
                *(float4*)(Vs + vr * VSTRIDE + vd) =
                    *(const float4*)(Vg + (size_t)vr * HID + vd);
            }
        }
        __syncthreads();

        // ---- S = (Q K^T) via tf32 mma: warp tile 16x32 ----
        {
            float accS[4][4];
#pragma unroll
            for (int nt = 0; nt < 4; nt++)
#pragma unroll
                for (int e = 0; e < 4; e++) accS[nt][e] = 0.f;

#pragma unroll
            for (int ch = 0; ch < 4; ch++) {
                const float* qa = Qs + ch * 2048;
                const float* kb = Ks + ch * 2048;
#pragma unroll
                for (int half = 0; half < 2; half++) {
                    const int q = 2 * csel + half;
                    int r0 = warpM * 16 + g;
                    int r8 = r0 + 8;
                    float4 A0 = *(const float4*)(qa + r0 * 32 + ((q ^ (r0 & 7)) * 4));
                    float4 A8 = *(const float4*)(qa + r8 * 32 + ((q ^ (r8 & 7)) * 4));
#pragma unroll
                    for (int nt = 0; nt < 4; nt++) {
                        int n = warpN * 32 + nt * 8 + g;
                        float4 Bf = *(const float4*)(kb + n * 32 + ((q ^ (n & 7)) * 4));
                        mma_tf32(accS[nt][0], accS[nt][1], accS[nt][2], accS[nt][3],
                                 A0.x, A8.x, A0.y, A8.y, Bf.x, Bf.y);
                        mma_tf32(accS[nt][0], accS[nt][1], accS[nt][2], accS[nt][3],
                                 A0.z, A8.z, A0.w, A8.w, Bf.z, Bf.w);
                    }
                }
            }
            // write S (scaled) to Ss
            int row0 = warpM * 16 + g;
#pragma unroll
            for (int nt = 0; nt < 4; nt++) {
                int col = warpN * 32 + nt * 8 + 2 * csel;
                *(float2*)(Ss + row0 * SSTRIDE + col) =
                    make_float2(accS[nt][0] * scale, accS[nt][1] * scale);
                *(float2*)(Ss + (row0 + 8) * SSTRIDE + col) =
                    make_float2(accS[nt][2] * scale, accS[nt][3] * scale);
            }
        }
        __syncthreads();

        // ---- online softmax: 4 threads per row ----
        {
            const int r  = tid >> 2;
            const int qd = tid & 3;
            float* srow = Ss + r * SSTRIDE + qd * 16;
            float mold = m_s[r];
            float mx = mold;
#pragma unroll
            for (int c = 0; c < 16; c++) mx = fmaxf(mx, srow[c]);
            mx = fmaxf(mx, __shfl_xor_sync(0xFFFFFFFFu, mx, 1));
            mx = fmaxf(mx, __shfl_xor_sync(0xFFFFFFFFu, mx, 2));
            float ls = 0.f;
#pragma unroll
            for (int c = 0; c < 16; c++) {
                float p = __expf(srow[c] - mx);
                srow[c] = p;
                ls += p;
            }
            ls += __shfl_xor_sync(0xFFFFFFFFu, ls, 1);
            ls += __shfl_xor_sync(0xFFFFFFFFu, ls, 2);
            if (qd == 0) {
                float alpha = __expf(mold - mx);
                m_s[r] = mx;
                l_s[r] = l_s[r] * alpha + ls;
                a_s[r] = alpha;
            }
        }
        __syncthreads();

        // ---- O update: acc = acc*alpha + P @ V (fp32) ----
        {
#pragma unroll
            for (int i = 0; i < 4; i++) {
                float al = a_s[pr0 + i];
#pragma unroll
                for (int j = 0; j < 8; j++) accO[i][j] *= al;
            }
#pragma unroll 4
            for (int c = 0; c < 64; c++) {
                float4 vA = *(const float4*)(Vs + c * VSTRIDE + cA);
                float4 vB = *(const float4*)(Vs + c * VSTRIDE + cB);
#pragma unroll
                for (int i = 0; i < 4; i++) {
                    float p = Ss[(pr0 + i) * SSTRIDE + c];
                    accO[i][0] = fmaf(p, vA.x, accO[i][0]);
                    accO[i][1] = fmaf(p, vA.y, accO[i][1]);
                    accO[i][2] = fmaf(p, vA.z, accO[i][2]);
                    accO[i][3] = fmaf(p, vA.w, accO[i][3]);
                    accO[i][4] = fmaf(p, vB.x, accO[i][4]);
                    accO[i][5] = fmaf(p, vB.y, accO[i][5]);
                    accO[i][6] = fmaf(p, vB.z, accO[i][6]);
                    accO[i][7] = fmaf(p, vB.w, accO[i][7]);
                }
            }
        }
    }

    // ---- normalize + scatter to permuted context layout ----
    {
#pragma unroll
        for (int i = 0; i < 4; i++) {
            int   s_g     = q0 + pr0 + i;
            float inv     = 1.f / l_s[pr0 + i];
            int   srow_hi = s_g >> 7;
            int   srow_lo = s_g & 127;
            size_t base = (size_t)b * ((size_t)SEQ * HID)
                        + (size_t)srow_lo * NHEADS + h;
#pragma unroll
            for (int e = 0; e < 4; e++) {
                int dA = cA + e;
                int dB = cB + e;
                g_CTX[base + (size_t)(dA * NHEADS + srow_hi) * HID] = accO[i][e]     * inv;
                g_CTX[base + (size_t)(dB * NHEADS + srow_hi) * HID] = accO[i][4 + e] * inv;
            }
        }
    }
}

// ---------------------------------------------------------------------------
// Launch
// ---------------------------------------------------------------------------
extern "C" void kernel_launch(void* const* d_in, const int* in_sizes, int n_in,
                              void* d_out, int out_size)
{
    (void)in_sizes; (void)n_in; (void)out_size;
    const float* X  = (const float*)d_in[0];
    const float* Wq = (const float*)d_in[1];
    const float* bq = (const float*)d_in[2];
    const float* Wk = (const float*)d_in[3];
    const float* bk = (const float*)d_in[4];
    const float* Wv = (const float*)d_in[5];
    const float* bv = (const float*)d_in[6];
    const float* Wo = (const float*)d_in[7];
    const float* bo = (const float*)d_in[8];
    float* out = (float*)d_out;

    cudaFuncSetAttribute(qkv_gemm_tc, cudaFuncAttributeMaxDynamicSharedMemorySize,
                         GEMM_SMEM_BYTES);
    cudaFuncSetAttribute(out_gemm_tc, cudaFuncAttributeMaxDynamicSharedMemorySize,
                         GEMM_SMEM_BYTES);
    cudaFuncSetAttribute(attn_kernel, cudaFuncAttributeMaxDynamicSharedMemorySize,
                         ATTN_SMEM_BYTES);

    dim3 gq(HID / 128, MROWS / 128, 3);
    qkv_gemm_tc<<<gq, 256, GEMM_SMEM_BYTES>>>(X, Wq, bq, Wk, bk, Wv, bv);

    dim3 ga(SEQ / 64, BATCH * NHEADS);
    attn_kernel<<<ga, 256, ATTN_SMEM_BYTES>>>();

    dim3 go(HID / 128, MROWS / 128, 1);
    out_gemm_tc<<<go, 256, GEMM_SMEM_BYTES>>>(Wo, bo, out);
}

// round 8
// speedup vs baseline: 4.0109x; 1.4239x over previous
#include <cuda_runtime.h>
#include <math.h>
#include <stdint.h>

// Problem constants
#define HID    2048
#define BATCH  2
#define SEQ    2048
#define NHEADS 16
#define HD     128
#define MROWS  (BATCH * SEQ)   // 4096

// ---------------------------------------------------------------------------
// Scratch (static __device__ arrays — no allocation anywhere)
// ---------------------------------------------------------------------------
__device__ float g_Q[(size_t)MROWS * HID];
__device__ float g_K[(size_t)MROWS * HID];
__device__ float g_V[(size_t)MROWS * HID];
__device__ float g_CTX[(size_t)MROWS * HID];

// ---------------------------------------------------------------------------
// Helpers
// ---------------------------------------------------------------------------
__device__ __forceinline__ float f2tf32f(float f) {
    uint32_t r;
    asm("cvt.rna.tf32.f32 %0, %1;" : "=r"(r) : "f"(f));
    return __uint_as_float(r);
}

__device__ __forceinline__ void mma_tf32(float& d0, float& d1, float& d2, float& d3,
                                         float a0, float a1, float a2, float a3,
                                         float b0, float b1)
{
    asm volatile(
        "mma.sync.aligned.m16n8k8.row.col.f32.tf32.tf32.f32 "
        "{%0,%1,%2,%3}, {%4,%5,%6,%7}, {%8,%9}, {%0,%1,%2,%3};"
        : "+f"(d0), "+f"(d1), "+f"(d2), "+f"(d3)
        : "r"(__float_as_uint(a0)), "r"(__float_as_uint(a1)),
          "r"(__float_as_uint(a2)), "r"(__float_as_uint(a3)),
          "r"(__float_as_uint(b0)), "r"(__float_as_uint(b1)));
}

// ---------------------------------------------------------------------------
// tf32 mma.sync GEMM: C[4096,2048] = A[4096,2048] @ W[2048,2048] + bias
// (proven R6 design: permuted A layout + padded B layout, conflict-free)
// ---------------------------------------------------------------------------
#define BSTRIDE 136
#define GEMM_SMEM_FLOATS (2 * 4096 + 2 * (32 * BSTRIDE))
#define GEMM_SMEM_BYTES  (GEMM_SMEM_FLOATS * 4)

__device__ __forceinline__ void tf32_gemm_body(const float* __restrict__ A,
                                               const float* __restrict__ W,
                                               const float* __restrict__ bias,
                                               float* __restrict__ C)
{
    extern __shared__ float sm[];
    float* smA = sm;                    // 2 stages x 4096
    float* smB = sm + 8192;             // 2 stages x 4352

    const int tid   = threadIdx.x;
    const int lane  = tid & 31;
    const int wid   = tid >> 5;
    const int warpM = wid >> 2;      // 0..1
    const int warpN = wid & 3;       // 0..3
    const int csel  = lane & 3;
    const int g     = lane >> 2;

    const int m0 = blockIdx.y * 128;
    const int n0 = blockIdx.x * 128;

    const float* Abase = A + (size_t)m0 * HID;
    const float* Wbase = W + n0;

    float4 stA[4], stB[4];

    auto ldg_chunk = [&](int kt) {
        const float* Ag = Abase + kt * 32;
#pragma unroll
        for (int i = 0; i < 4; i++) {
            int idx = tid + i * 256;
            int r = idx >> 3;
            int j = idx & 7;
            stA[i] = *(const float4*)(Ag + (size_t)r * HID + j * 4);
        }
        const float* Wg = Wbase + (size_t)(kt * 32) * HID;
#pragma unroll
        for (int i = 0; i < 4; i++) {
            int idx = tid + i * 256;
            int k  = idx >> 5;
            int jn = idx & 31;
            stB[i] = *(const float4*)(Wg + (size_t)k * HID + jn * 4);
        }
    };

    auto sts_chunk = [&](int s) {
        float* a = smA + s * 4096;
        float* b = smB + s * (32 * BSTRIDE);
#pragma unroll
        for (int i = 0; i < 4; i++) {
            int idx = tid + i * 256;
            int r = idx >> 3;
            int j = idx & 7;
            const float v[4] = { stA[i].x, stA[i].y, stA[i].z, stA[i].w };
#pragma unroll
            for (int e = 0; e < 4; e++) {
                int p     = e * 8 + j;
                int chunk = (p >> 2) ^ (r & 7);
                a[r * 32 + chunk * 4 + (p & 3)] = f2tf32f(v[e]);
            }
        }
#pragma unroll
        for (int i = 0; i < 4; i++) {
            int idx = tid + i * 256;
            int k  = idx >> 5;
            int jn = idx & 31;
            float4 t;
            t.x = f2tf32f(stB[i].x);
            t.y = f2tf32f(stB[i].y);
            t.z = f2tf32f(stB[i].z);
            t.w = f2tf32f(stB[i].w);
            *(float4*)(b + k * BSTRIDE + jn * 4) = t;
        }
    };

    float acc[4][4][4];
#pragma unroll
    for (int mt = 0; mt < 4; mt++)
#pragma unroll
        for (int nt = 0; nt < 4; nt++)
#pragma unroll
            for (int e = 0; e < 4; e++) acc[mt][nt][e] = 0.f;

    auto compute = [&](int s) {
        const float* a = smA + s * 4096;
        const float* b = smB + s * (32 * BSTRIDE);
#pragma unroll
        for (int half = 0; half < 2; half++) {
            const int q = 2 * csel + half;
            float4 A0[4], A8[4];
#pragma unroll
            for (int mt = 0; mt < 4; mt++) {
                int r0 = warpM * 64 + mt * 16 + g;
                int r8 = r0 + 8;
                A0[mt] = *(const float4*)(a + r0 * 32 + ((q ^ (r0 & 7)) * 4));
                A8[mt] = *(const float4*)(a + r8 * 32 + ((q ^ (r8 & 7)) * 4));
            }
            const int kb = csel + 16 * half;
#pragma unroll
            for (int nt = 0; nt < 4; nt++) {
                int n = warpN * 32 + nt * 8 + g;
                const float* bp = b + n;
                float b0 = bp[(kb + 0)  * BSTRIDE];
                float b1 = bp[(kb + 4)  * BSTRIDE];
                float b2 = bp[(kb + 8)  * BSTRIDE];
                float b3 = bp[(kb + 12) * BSTRIDE];
#pragma unroll
                for (int mt = 0; mt < 4; mt++) {
                    mma_tf32(acc[mt][nt][0], acc[mt][nt][1],
                             acc[mt][nt][2], acc[mt][nt][3],
                             A0[mt].x, A8[mt].x, A0[mt].y, A8[mt].y, b0, b1);
                    mma_tf32(acc[mt][nt][0], acc[mt][nt][1],
                             acc[mt][nt][2], acc[mt][nt][3],
                             A0[mt].z, A8[mt].z, A0[mt].w, A8[mt].w, b2, b3);
                }
            }
        }
    };

    ldg_chunk(0);
    sts_chunk(0);
    __syncthreads();

    for (int c = 0; c < HID / 32; c++) {
        const int s = c & 1;
        if (c < HID / 32 - 1) ldg_chunk(c + 1);
        compute(s);
        if (c < HID / 32 - 1) {
            sts_chunk(s ^ 1);
            __syncthreads();
        }
    }

#pragma unroll
    for (int mt = 0; mt < 4; mt++) {
        int row = m0 + warpM * 64 + mt * 16 + g;
#pragma unroll
        for (int nt = 0; nt < 4; nt++) {
            int col = n0 + warpN * 32 + nt * 8 + 2 * csel;
            float b0 = __ldg(bias + col);
            float b1 = __ldg(bias + col + 1);
            float2 lo = make_float2(acc[mt][nt][0] + b0, acc[mt][nt][1] + b1);
            float2 hi = make_float2(acc[mt][nt][2] + b0, acc[mt][nt][3] + b1);
            *(float2*)(C + (size_t)row * HID + col)       = lo;
            *(float2*)(C + (size_t)(row + 8) * HID + col) = hi;
        }
    }
}

__global__ __launch_bounds__(256)
void qkv_gemm_tc(const float* __restrict__ X,
                 const float* __restrict__ Wq, const float* __restrict__ bq,
                 const float* __restrict__ Wk, const float* __restrict__ bk,
                 const float* __restrict__ Wv, const float* __restrict__ bv)
{
    const float* W; const float* b; float* Cp;
    if (blockIdx.z == 0)      { W = Wq; b = bq; Cp = g_Q; }
    else if (blockIdx.z == 1) { W = Wk; b = bk; Cp = g_K; }
    else                      { W = Wv; b = bv; Cp = g_V; }
    tf32_gemm_body(X, W, b, Cp);
}

__global__ __launch_bounds__(256)
void out_gemm_tc(const float* __restrict__ Wo, const float* __restrict__ bo,
                 float* __restrict__ out)
{
    tf32_gemm_body(g_CTX, Wo, bo, out);
}

// ---------------------------------------------------------------------------
// Attention v3: QK^T AND PV both via tf32 mma.
//   S-mma: permuted Q/K layouts (R6, proven).
//   PV-mma: P row-major in Ss (stride 68 -> conflict-free A-frags),
//           V natural [key][d] in Vs (stride 136 -> conflict-free B-frags).
//   P and V are RNA-rounded to tf32 to avoid mma truncation bias.
//   Online-softmax rescale applied to C-fragments.
// One CTA = (b,h) x 64 query rows. Output scattered to permuted ctx layout:
//   ctx[b][d*16 + s/128][(s%128)*16 + h].
// ---------------------------------------------------------------------------
#define SSTRIDE 68
#define VSTRIDE 136
// floats: Qs 8192 | Ks 8192 | Vs 64*136=8704 | Ss 64*68=4352 | m/l/a 192
#define ATTN_SMEM_FLOATS (8192 + 8192 + 8704 + 4352 + 192)
#define ATTN_SMEM_BYTES  (ATTN_SMEM_FLOATS * 4)

__global__ __launch_bounds__(256)
void attn_kernel()
{
    extern __shared__ float smf[];
    float* Qs  = smf;                    // 4 chunks x 64 x 32 (permuted tf32)
    float* Ks  = Qs + 8192;              // 4 chunks x 64 x 32 (permuted tf32)
    float* Vs  = Ks + 8192;              // 64 x VSTRIDE (tf32 values)
    float* Ss  = Vs + 8704;              // 64 x SSTRIDE
    float* m_s = Ss + 64 * SSTRIDE;      // 64
    float* l_s = m_s + 64;               // 64
    float* a_s = l_s + 64;               // 64

    const int tid  = threadIdx.x;
    const int lane = tid & 31;
    const int wid  = tid >> 5;
    const int warpM = wid >> 1;      // 0..3  (16-row slabs)
    const int warpN = wid & 1;       // 0..1
    const int csel  = lane & 3;
    const int g     = lane >> 2;

    const int bh  = blockIdx.y;
    const int b   = bh >> 4;
    const int h   = bh & 15;
    const int q0  = blockIdx.x * 64;
    const size_t rowbase = (size_t)b * SEQ;
    const float scale = 0.08838834764831845f;   // 1/sqrt(128)

    const int pm0 = warpM * 16;      // row slab (both S and O)
    const int pn0 = warpN * 64;      // O col slab (PV)

    // ---- load Q tile (64 x 128) into permuted tf32 layout ----
    {
        const float* Qg = g_Q + (rowbase + q0) * HID + h * HD;
#pragma unroll
        for (int it = 0; it < 8; it++) {
            int idx  = tid + it * 256;
            int ch   = idx >> 9;
            int idx2 = idx & 511;
            int r    = idx2 >> 3;
            int j    = idx2 & 7;
            float4 v = *(const float4*)(Qg + (size_t)r * HID + ch * 32 + j * 4);
            float* dst = Qs + ch * 2048;
            const float vv[4] = { v.x, v.y, v.z, v.w };
#pragma unroll
            for (int e = 0; e < 4; e++) {
                int p     = e * 8 + j;
                int chunk = (p >> 2) ^ (r & 7);
                dst[r * 32 + chunk * 4 + (p & 3)] = f2tf32f(vv[e]);
            }
        }
    }
    if (tid < 64) { m_s[tid] = -INFINITY; l_s[tid] = 0.f; }

    // O accumulator as C-fragments: 8 n-tiles x 4
    float accO[8][4];
#pragma unroll
    for (int nt = 0; nt < 8; nt++)
#pragma unroll
        for (int e = 0; e < 4; e++) accO[nt][e] = 0.f;

    for (int jt = 0; jt < SEQ / 64; jt++) {
        __syncthreads();   // prior-iter readers of Ks/Vs/Ss done

        // ---- load K tile (permuted tf32) + V tile (tf32, stride 136) ----
        {
            const float* Kg = g_K + (rowbase + jt * 64) * HID + h * HD;
            const float* Vg = g_V + (rowbase + jt * 64) * HID + h * HD;
#pragma unroll
            for (int it = 0; it < 8; it++) {
                int idx  = tid + it * 256;
                int ch   = idx >> 9;
                int idx2 = idx & 511;
                int r    = idx2 >> 3;
                int j    = idx2 & 7;
                float4 v = *(const float4*)(Kg + (size_t)r * HID + ch * 32 + j * 4);
                float* dst = Ks + ch * 2048;
                const float vv[4] = { v.x, v.y, v.z, v.w };
#pragma unroll
                for (int e = 0; e < 4; e++) {
                    int p     = e * 8 + j;
                    int chunk = (p >> 2) ^ (r & 7);
                    dst[r * 32 + chunk * 4 + (p & 3)] = f2tf32f(vv[e]);
                }
                int vr = idx >> 5;            // const per (warp, it)
                int vd = (idx & 31) * 4;
                float4 vv4 = *(const float4*)(Vg + (size_t)vr * HID + vd);
                float4 t;
                t.x = f2tf32f(vv4.x); t.y = f2tf32f(vv4.y);
                t.z = f2tf32f(vv4.z); t.w = f2tf32f(vv4.w);
                *(float4*)(Vs + vr * VSTRIDE + vd) = t;
            }
        }
        __syncthreads();

        // ---- S = (Q K^T) via tf32 mma: warp tile 16x32 ----
        {
            float accS[4][4];
#pragma unroll
            for (int nt = 0; nt < 4; nt++)
#pragma unroll
                for (int e = 0; e < 4; e++) accS[nt][e] = 0.f;

#pragma unroll
            for (int ch = 0; ch < 4; ch++) {
                const float* qa = Qs + ch * 2048;
                const float* kb = Ks + ch * 2048;
#pragma unroll
                for (int half = 0; half < 2; half++) {
                    const int q = 2 * csel + half;
                    int r0 = pm0 + g;
                    int r8 = r0 + 8;
                    float4 A0 = *(const float4*)(qa + r0 * 32 + ((q ^ (r0 & 7)) * 4));
                    float4 A8 = *(const float4*)(qa + r8 * 32 + ((q ^ (r8 & 7)) * 4));
#pragma unroll
                    for (int nt = 0; nt < 4; nt++) {
                        int n = warpN * 32 + nt * 8 + g;
                        float4 Bf = *(const float4*)(kb + n * 32 + ((q ^ (n & 7)) * 4));
                        mma_tf32(accS[nt][0], accS[nt][1], accS[nt][2], accS[nt][3],
                                 A0.x, A8.x, A0.y, A8.y, Bf.x, Bf.y);
                        mma_tf32(accS[nt][0], accS[nt][1], accS[nt][2], accS[nt][3],
                                 A0.z, A8.z, A0.w, A8.w, Bf.z, Bf.w);
                    }
                }
            }
            int row0 = pm0 + g;
#pragma unroll
            for (int nt = 0; nt < 4; nt++) {
                int col = warpN * 32 + nt * 8 + 2 * csel;
                *(float2*)(Ss + row0 * SSTRIDE + col) =
                    make_float2(accS[nt][0] * scale, accS[nt][1] * scale);
                *(float2*)(Ss + (row0 + 8) * SSTRIDE + col) =
                    make_float2(accS[nt][2] * scale, accS[nt][3] * scale);
            }
        }
        __syncthreads();

        // ---- online softmax: 4 threads per row; P stored tf32-rounded ----
        {
            const int r  = tid >> 2;
            const int qd = tid & 3;
            float* srow = Ss + r * SSTRIDE + qd * 16;
            float mold = m_s[r];
            float mx = mold;
#pragma unroll
            for (int c = 0; c < 16; c++) mx = fmaxf(mx, srow[c]);
            mx = fmaxf(mx, __shfl_xor_sync(0xFFFFFFFFu, mx, 1));
            mx = fmaxf(mx, __shfl_xor_sync(0xFFFFFFFFu, mx, 2));
            float ls = 0.f;
#pragma unroll
            for (int c = 0; c < 16; c++) {
                float p = __expf(srow[c] - mx);
                srow[c] = f2tf32f(p);
                ls += p;
            }
            ls += __shfl_xor_sync(0xFFFFFFFFu, ls, 1);
            ls += __shfl_xor_sync(0xFFFFFFFFu, ls, 2);
            if (qd == 0) {
                float alpha = __expf(mold - mx);
                m_s[r] = mx;
                l_s[r] = l_s[r] * alpha + ls;
                a_s[r] = alpha;
            }
        }
        __syncthreads();

        // ---- O += P @ V via tf32 mma (C-fragment rescale by alpha) ----
        {
            float al0 = a_s[pm0 + g];
            float al1 = a_s[pm0 + g + 8];
#pragma unroll
            for (int nt = 0; nt < 8; nt++) {
                accO[nt][0] *= al0;  accO[nt][1] *= al0;
                accO[nt][2] *= al1;  accO[nt][3] *= al1;
            }
            const float* Pr0 = Ss + (pm0 + g) * SSTRIDE;
            const float* Pr8 = Pr0 + 8 * SSTRIDE;
#pragma unroll
            for (int kk = 0; kk < 8; kk++) {
                const int k0 = kk * 8;
                float a0 = Pr0[k0 + csel];
                float a1 = Pr8[k0 + csel];
                float a2 = Pr0[k0 + csel + 4];
                float a3 = Pr8[k0 + csel + 4];
                const float* Vk0 = Vs + (k0 + csel) * VSTRIDE + pn0 + g;
                const float* Vk4 = Vk0 + 4 * VSTRIDE;
#pragma unroll
                for (int nt = 0; nt < 8; nt++) {
                    float b0 = Vk0[nt * 8];
                    float b1 = Vk4[nt * 8];
                    mma_tf32(accO[nt][0], accO[nt][1], accO[nt][2], accO[nt][3],
                             a0, a1, a2, a3, b0, b1);
                }
            }
        }
    }

    // ---- normalize + scatter C-fragments to permuted ctx layout ----
    {
        float inv0 = 1.f / l_s[pm0 + g];
        float inv1 = 1.f / l_s[pm0 + g + 8];
        int s0 = q0 + pm0 + g;
        int s1 = s0 + 8;
        size_t base0 = (size_t)b * ((size_t)SEQ * HID)
                     + (size_t)(s0 & 127) * NHEADS + h + (size_t)(s0 >> 7) * HID;
        size_t base1 = (size_t)b * ((size_t)SEQ * HID)
                     + (size_t)(s1 & 127) * NHEADS + h + (size_t)(s1 >> 7) * HID;
#pragma unroll
        for (int nt = 0; nt < 8; nt++) {
            int d0 = pn0 + nt * 8 + 2 * csel;
            size_t o00 = base0 + (size_t)(d0 * NHEADS) * HID;
            size_t o01 = o00 + (size_t)NHEADS * HID;
            size_t o10 = base1 + (size_t)(d0 * NHEADS) * HID;
            size_t o11 = o10 + (size_t)NHEADS * HID;
            g_CTX[o00] = accO[nt][0] * inv0;
            g_CTX[o01] = accO[nt][1] * inv0;
            g_CTX[o10] = accO[nt][2] * inv1;
            g_CTX[o11] = accO[nt][3] * inv1;
        }
    }
}

// ---------------------------------------------------------------------------
// Launch
// ---------------------------------------------------------------------------
extern "C" void kernel_launch(void* const* d_in, const int* in_sizes, int n_in,
                              void* d_out, int out_size)
{
    (void)in_sizes; (void)n_in; (void)out_size;
    const float* X  = (const float*)d_in[0];
    const float* Wq = (const float*)d_in[1];
    const float* bq = (const float*)d_in[2];
    const float* Wk = (const float*)d_in[3];
    const float* bk = (const float*)d_in[4];
    const float* Wv = (const float*)d_in[5];
    const float* bv = (const float*)d_in[6];
    const float* Wo = (const float*)d_in[7];
    const float* bo = (const float*)d_in[8];
    float* out = (float*)d_out;

    cudaFuncSetAttribute(qkv_gemm_tc, cudaFuncAttributeMaxDynamicSharedMemorySize,
                         GEMM_SMEM_BYTES);
    cudaFuncSetAttribute(out_gemm_tc, cudaFuncAttributeMaxDynamicSharedMemorySize,
                         GEMM_SMEM_BYTES);
    cudaFuncSetAttribute(attn_kernel, cudaFuncAttributeMaxDynamicSharedMemorySize,
                         ATTN_SMEM_BYTES);

    dim3 gq(HID / 128, MROWS / 128, 3);
    qkv_gemm_tc<<<gq, 256, GEMM_SMEM_BYTES>>>(X, Wq, bq, Wk, bk, Wv, bv);

    dim3 ga(SEQ / 64, BATCH * NHEADS);
    attn_kernel<<<ga, 256, ATTN_SMEM_BYTES>>>();

    dim3 go(HID / 128, MROWS / 128, 1);
    out_gemm_tc<<<go, 256, GEMM_SMEM_BYTES>>>(Wo, bo, out);
}

// round 9
// speedup vs baseline: 5.1268x; 1.2782x over previous
#include <cuda_runtime.h>
#include <math.h>
#include <stdint.h>

// Problem constants
#define HID    2048
#define BATCH  2
#define SEQ    2048
#define NHEADS 16
#define HD     128
#define MROWS  (BATCH * SEQ)   // 4096

// ---------------------------------------------------------------------------
// Scratch (static __device__ arrays — no allocation anywhere)
// ---------------------------------------------------------------------------
__device__ float g_Xp [(size_t)MROWS * HID];          // X, tf32, permuted A layout
__device__ float g_Wp [(size_t)4 * HID * HID];        // Wq,Wk,Wv,Wo tf32 (orig layout)
__device__ float g_Q  [(size_t)MROWS * HID];          // Q tf32, permuted per-head
__device__ float g_K  [(size_t)MROWS * HID];          // K tf32, permuted per-head
__device__ float g_V  [(size_t)MROWS * HID];          // V tf32, plain
__device__ float g_CTXp[(size_t)MROWS * HID];         // ctx tf32, permuted A layout

// ---------------------------------------------------------------------------
// Helpers
// ---------------------------------------------------------------------------
__device__ __forceinline__ float f2tf32f(float f) {
    uint32_t r;
    asm("cvt.rna.tf32.f32 %0, %1;" : "=r"(r) : "f"(f));
    return __uint_as_float(r);
}
__device__ __forceinline__ uint32_t smem_u32(const void* p) {
    uint32_t a;
    asm("{ .reg .u64 t; cvta.to.shared.u64 t, %1; cvt.u32.u64 %0, t; }"
        : "=r"(a) : "l"(p));
    return a;
}
__device__ __forceinline__ void cp16(uint32_t dst, const void* src) {
    asm volatile("cp.async.cg.shared.global [%0], [%1], 16;"
                 :: "r"(dst), "l"(src));
}
__device__ __forceinline__ void cp_commit() {
    asm volatile("cp.async.commit_group;");
}
template <int N>
__device__ __forceinline__ void cp_wait() {
    asm volatile("cp.async.wait_group %0;" :: "n"(N));
}

__device__ __forceinline__ void mma_tf32(float& d0, float& d1, float& d2, float& d3,
                                         float a0, float a1, float a2, float a3,
                                         float b0, float b1)
{
    asm volatile(
        "mma.sync.aligned.m16n8k8.row.col.f32.tf32.tf32.f32 "
        "{%0,%1,%2,%3}, {%4,%5,%6,%7}, {%8,%9}, {%0,%1,%2,%3};"
        : "+f"(d0), "+f"(d1), "+f"(d2), "+f"(d3)
        : "r"(__float_as_uint(a0)), "r"(__float_as_uint(a1)),
          "r"(__float_as_uint(a2)), "r"(__float_as_uint(a3)),
          "r"(__float_as_uint(b0)), "r"(__float_as_uint(b1)));
}

// ---------------------------------------------------------------------------
// Prep: z=0 -> X to permuted-tf32 g_Xp ; z=1..4 -> W* to tf32 g_Wp
// Permuted A layout (per 32-float k-block of each row r):
//   element (r, kin) stored at  ((p>>2) ^ (r&7))*4 + (p&3),  p=(kin%4)*8+kin/4
// ---------------------------------------------------------------------------
__global__ __launch_bounds__(256)
void prep_kernel(const float* __restrict__ X,
                 const float* __restrict__ Wq, const float* __restrict__ Wk,
                 const float* __restrict__ Wv, const float* __restrict__ Wo)
{
    const int idx = blockIdx.x * 256 + threadIdx.x;   // float4 index
    const int z = blockIdx.z;
    if (z == 0) {
        // X: 4096 x 2048 -> 2M float4
        int r   = idx >> 9;            // row
        int rem = idx & 511;
        int c   = rem >> 3;            // 32-float block
        int j   = rem & 7;             // float4 within block
        float4 v = *(const float4*)(X + (size_t)r * HID + c * 32 + j * 4);
        float* dst = g_Xp + (size_t)r * HID + c * 32;
        const float vv[4] = { v.x, v.y, v.z, v.w };
#pragma unroll
        for (int e = 0; e < 4; e++) {
            int p = e * 8 + j;
            dst[(((p >> 2) ^ (r & 7)) << 2) + (p & 3)] = f2tf32f(vv[e]);
        }
    } else {
        if (idx >= (HID * HID / 4)) return;
        const float* W = (z == 1) ? Wq : (z == 2) ? Wk : (z == 3) ? Wv : Wo;
        float4 v = *(const float4*)(W + (size_t)idx * 4);
        float4 t;
        t.x = f2tf32f(v.x); t.y = f2tf32f(v.y);
        t.z = f2tf32f(v.z); t.w = f2tf32f(v.w);
        *(float4*)(g_Wp + (size_t)(z - 1) * HID * HID + (size_t)idx * 4) = t;
    }
}

// ---------------------------------------------------------------------------
// tf32 mma.sync GEMM v3: C = Aperm @ Wp + bias
// cp.async 3-stage pipeline, 2 CTAs/SM. CTA 128x128, BK=32, 8 warps (2Mx4N).
// mode 0: store tf32, permuted per-head layout (for Q, K)
// mode 1: store tf32, plain layout (for V)
// mode 2: store fp32, plain layout (final output)
// ---------------------------------------------------------------------------
#define NSTAGE   3
#define ASTG     4096                       // floats per A stage
#define BSTRIDE  136
#define BSTG     (32 * BSTRIDE)             // 4352 floats per B stage
#define GEMM_SMEM_FLOATS (NSTAGE * (ASTG + BSTG))
#define GEMM_SMEM_BYTES  (GEMM_SMEM_FLOATS * 4)

__device__ __forceinline__ void tf32_gemm_body(const float* __restrict__ Ap,
                                               const float* __restrict__ Wp,
                                               const float* __restrict__ bias,
                                               float* __restrict__ C,
                                               int mode)
{
    extern __shared__ float sm[];
    float* smA = sm;                     // NSTAGE x ASTG
    float* smB = sm + NSTAGE * ASTG;     // NSTAGE x BSTG
    const uint32_t smA_u = smem_u32(smA);
    const uint32_t smB_u = smem_u32(smB);

    const int tid   = threadIdx.x;
    const int lane  = tid & 31;
    const int wid   = tid >> 5;
    const int warpM = wid >> 2;
    const int warpN = wid & 3;
    const int csel  = lane & 3;
    const int g     = lane >> 2;

    const int m0 = blockIdx.y * 128;
    const int n0 = blockIdx.x * 128;

    // Precomputed loader coords
    const int la_r = tid >> 3;            // base row for A loader (i adds 32)
    const int la_j = tid & 7;
    const int lb_k = tid >> 5;            // base k for B loader (i adds 8)
    const int lb_j = tid & 31;

    const float* Abase = Ap + (size_t)m0 * HID + la_r * HID + la_j * 4;
    const float* Bbase = Wp + (size_t)lb_k * HID + n0 + lb_j * 4;
    const uint32_t dA = smA_u + (la_r * 32 + la_j * 4) * 4;
    const uint32_t dB = smB_u + (lb_k * BSTRIDE + lb_j * 4) * 4;

    auto load_chunk = [&](int c, int st) {
        const float* As = Abase + c * 32;
        const uint32_t dAs = dA + st * (ASTG * 4);
#pragma unroll
        for (int i = 0; i < 4; i++)
            cp16(dAs + i * 32 * 32 * 4, As + (size_t)i * 32 * HID);
        const float* Bs = Bbase + (size_t)(c * 32) * HID;
        const uint32_t dBs = dB + st * (BSTG * 4);
#pragma unroll
        for (int i = 0; i < 4; i++)
            cp16(dBs + i * 8 * BSTRIDE * 4, Bs + (size_t)i * 8 * HID);
        cp_commit();
    };

    float acc[4][4][4];
#pragma unroll
    for (int mt = 0; mt < 4; mt++)
#pragma unroll
        for (int nt = 0; nt < 4; nt++)
#pragma unroll
            for (int e = 0; e < 4; e++) acc[mt][nt][e] = 0.f;

    auto compute = [&](int st) {
        const float* a = smA + st * ASTG;
        const float* b = smB + st * BSTG;
#pragma unroll
        for (int half = 0; half < 2; half++) {
            const int q = 2 * csel + half;
            float4 A0[4], A8[4];
#pragma unroll
            for (int mt = 0; mt < 4; mt++) {
                int r0 = warpM * 64 + mt * 16 + g;
                int r8 = r0 + 8;
                A0[mt] = *(const float4*)(a + r0 * 32 + ((q ^ (r0 & 7)) * 4));
                A8[mt] = *(const float4*)(a + r8 * 32 + ((q ^ (r8 & 7)) * 4));
            }
            const int kb = csel + 16 * half;
#pragma unroll
            for (int nt = 0; nt < 4; nt++) {
                int n = warpN * 32 + nt * 8 + g;
                const float* bp = b + n;
                float b0 = bp[(kb + 0)  * BSTRIDE];
                float b1 = bp[(kb + 4)  * BSTRIDE];
                float b2 = bp[(kb + 8)  * BSTRIDE];
                float b3 = bp[(kb + 12) * BSTRIDE];
#pragma unroll
                for (int mt = 0; mt < 4; mt++) {
                    mma_tf32(acc[mt][nt][0], acc[mt][nt][1],
                             acc[mt][nt][2], acc[mt][nt][3],
                             A0[mt].x, A8[mt].x, A0[mt].y, A8[mt].y, b0, b1);
                    mma_tf32(acc[mt][nt][0], acc[mt][nt][1],
                             acc[mt][nt][2], acc[mt][nt][3],
                             A0[mt].z, A8[mt].z, A0[mt].w, A8[mt].w, b2, b3);
                }
            }
        }
    };

    load_chunk(0, 0);
    load_chunk(1, 1);

    const int NC = HID / 32;    // 64
    for (int c = 0; c < NC; c++) {
        if (c == NC - 1) cp_wait<0>(); else cp_wait<1>();
        __syncthreads();
        compute(c % NSTAGE);
        if (c + 2 < NC) load_chunk(c + 2, (c + 2) % NSTAGE);
    }

    // ---- epilogue ----
    if (mode == 0) {
        // permuted per-head tf32 store (Q, K for attention)
        const int xg = g & 7;
#pragma unroll
        for (int mt = 0; mt < 4; mt++) {
            int rg0 = m0 + warpM * 64 + mt * 16 + g;
            int rg1 = rg0 + 8;
#pragma unroll
            for (int nt = 0; nt < 4; nt++) {
                int kin0 = nt * 8 + 2 * csel;
                int colb = n0 + warpN * 32;
                int p0   = (kin0 & 3) * 8 + (kin0 >> 2);
                int x    = p0 >> 2, lo = p0 & 3;
                int idx0 = ((x ^ xg) << 2) + lo;
                int idx1 = (((x + 2) ^ xg) << 2) + lo;
                float b0 = __ldg(bias + colb + kin0);
                float b1 = __ldg(bias + colb + kin0 + 1);
                C[(size_t)rg0 * HID + colb + idx0] = f2tf32f(acc[mt][nt][0] + b0);
                C[(size_t)rg0 * HID + colb + idx1] = f2tf32f(acc[mt][nt][1] + b1);
                C[(size_t)rg1 * HID + colb + idx0] = f2tf32f(acc[mt][nt][2] + b0);
                C[(size_t)rg1 * HID + colb + idx1] = f2tf32f(acc[mt][nt][3] + b1);
            }
        }
    } else {
#pragma unroll
        for (int mt = 0; mt < 4; mt++) {
            int row = m0 + warpM * 64 + mt * 16 + g;
#pragma unroll
            for (int nt = 0; nt < 4; nt++) {
                int col = n0 + warpN * 32 + nt * 8 + 2 * csel;
                float b0 = __ldg(bias + col);
                float b1 = __ldg(bias + col + 1);
                float v0 = acc[mt][nt][0] + b0, v1 = acc[mt][nt][1] + b1;
                float v2 = acc[mt][nt][2] + b0, v3 = acc[mt][nt][3] + b1;
                if (mode == 1) {
                    v0 = f2tf32f(v0); v1 = f2tf32f(v1);
                    v2 = f2tf32f(v2); v3 = f2tf32f(v3);
                }
                *(float2*)(C + (size_t)row * HID + col)       = make_float2(v0, v1);
                *(float2*)(C + (size_t)(row + 8) * HID + col) = make_float2(v2, v3);
            }
        }
    }
}

__global__ __launch_bounds__(256, 2)
void qkv_gemm_tc(const float* __restrict__ bq,
                 const float* __restrict__ bk,
                 const float* __restrict__ bv)
{
    const float* Wz; const float* b; float* Cp; int mode;
    if (blockIdx.z == 0)      { Wz = g_Wp;                 b = bq; Cp = g_Q; mode = 0; }
    else if (blockIdx.z == 1) { Wz = g_Wp + (size_t)HID*HID;   b = bk; Cp = g_K; mode = 0; }
    else                      { Wz = g_Wp + (size_t)2*HID*HID; b = bv; Cp = g_V; mode = 1; }
    tf32_gemm_body(g_Xp, Wz, b, Cp, mode);
}

__global__ __launch_bounds__(256, 2)
void out_gemm_tc(const float* __restrict__ bo, float* __restrict__ out)
{
    tf32_gemm_body(g_CTXp, g_Wp + (size_t)3 * HID * HID, bo, out, 2);
}

// ---------------------------------------------------------------------------
// Attention v4: Q/K arrive pre-permuted tf32 (straight cp.async copies),
// V plain tf32. QK^T and PV via tf32 mma. Epilogue writes g_CTXp in the
// permuted A layout (tf32) so the O-projection gets the fast path.
// ---------------------------------------------------------------------------
#define SSTRIDE 68
#define VSTRIDE 136
#define ATTN_SMEM_FLOATS (8192 + 8192 + 64 * VSTRIDE + 64 * SSTRIDE + 192)
#define ATTN_SMEM_BYTES  (ATTN_SMEM_FLOATS * 4)

__global__ __launch_bounds__(256)
void attn_kernel()
{
    extern __shared__ float smf[];
    float* Qs  = smf;                    // 4 chunks x 64 x 32 (permuted tf32)
    float* Ks  = Qs + 8192;
    float* Vs  = Ks + 8192;              // 64 x VSTRIDE
    float* Ss  = Vs + 64 * VSTRIDE;      // 64 x SSTRIDE
    float* m_s = Ss + 64 * SSTRIDE;
    float* l_s = m_s + 64;
    float* a_s = l_s + 64;
    const uint32_t Qs_u = smem_u32(Qs);
    const uint32_t Ks_u = smem_u32(Ks);
    const uint32_t Vs_u = smem_u32(Vs);

    const int tid  = threadIdx.x;
    const int lane = tid & 31;
    const int wid  = tid >> 5;
    const int warpM = wid >> 1;
    const int warpN = wid & 1;
    const int csel  = lane & 3;
    const int g     = lane >> 2;

    const int bh  = blockIdx.y;
    const int b   = bh >> 4;
    const int h   = bh & 15;
    const int q0  = blockIdx.x * 64;
    const size_t rowbase = (size_t)b * SEQ;
    const float scale = 0.08838834764831845f;   // 1/sqrt(128)

    const int pm0 = warpM * 16;
    const int pn0 = warpN * 64;

    // loader coords: idx in [0,2048) float4 per tile; 8 iters x 256 threads
    // r = idx>>5 (row), rem = idx&31 (float4 within 128-float row)
    // ---- Q tile ----
    {
        const float* Qg = g_Q + (rowbase + q0) * HID + h * HD;
#pragma unroll
        for (int it = 0; it < 8; it++) {
            int idx = tid + it * 256;
            int r   = idx >> 5;
            int rem = idx & 31;
            cp16(Qs_u + (((rem >> 3) * 2048 + r * 32 + (rem & 7) * 4) * 4),
                 Qg + (size_t)r * HID + rem * 4);
        }
        cp_commit();
    }
    if (tid < 64) { m_s[tid] = -INFINITY; l_s[tid] = 0.f; }

    float accO[8][4];
#pragma unroll
    for (int nt = 0; nt < 8; nt++)
#pragma unroll
        for (int e = 0; e < 4; e++) accO[nt][e] = 0.f;

    cp_wait<0>();

    for (int jt = 0; jt < SEQ / 64; jt++) {
        __syncthreads();   // prior-iter readers of Ks/Vs/Ss done

        {
            const float* Kg = g_K + (rowbase + jt * 64) * HID + h * HD;
            const float* Vg = g_V + (rowbase + jt * 64) * HID + h * HD;
#pragma unroll
            for (int it = 0; it < 8; it++) {
                int idx = tid + it * 256;
                int r   = idx >> 5;
                int rem = idx & 31;
                cp16(Ks_u + (((rem >> 3) * 2048 + r * 32 + (rem & 7) * 4) * 4),
                     Kg + (size_t)r * HID + rem * 4);
                cp16(Vs_u + ((r * VSTRIDE + rem * 4) * 4),
                     Vg + (size_t)r * HID + rem * 4);
            }
            cp_commit();
            cp_wait<0>();
        }
        __syncthreads();

        // ---- S = (Q K^T) via tf32 mma: warp tile 16x32 ----
        {
            float accS[4][4];
#pragma unroll
            for (int nt = 0; nt < 4; nt++)
#pragma unroll
                for (int e = 0; e < 4; e++) accS[nt][e] = 0.f;

#pragma unroll
            for (int ch = 0; ch < 4; ch++) {
                const float* qa = Qs + ch * 2048;
                const float* kb = Ks + ch * 2048;
#pragma unroll
                for (int half = 0; half < 2; half++) {
                    const int q = 2 * csel + half;
                    int r0 = pm0 + g;
                    int r8 = r0 + 8;
                    float4 A0 = *(const float4*)(qa + r0 * 32 + ((q ^ (r0 & 7)) * 4));
                    float4 A8 = *(const float4*)(qa + r8 * 32 + ((q ^ (r8 & 7)) * 4));
#pragma unroll
                    for (int nt = 0; nt < 4; nt++) {
                        int n = warpN * 32 + nt * 8 + g;
                        float4 Bf = *(const float4*)(kb + n * 32 + ((q ^ (n & 7)) * 4));
                        mma_tf32(accS[nt][0], accS[nt][1], accS[nt][2], accS[nt][3],
                                 A0.x, A8.x, A0.y, A8.y, Bf.x, Bf.y);
                        mma_tf32(accS[nt][0], accS[nt][1], accS[nt][2], accS[nt][3],
                                 A0.z, A8.z, A0.w, A8.w, Bf.z, Bf.w);
                    }
                }
            }
            int row0 = pm0 + g;
#pragma unroll
            for (int nt = 0; nt < 4; nt++) {
                int col = warpN * 32 + nt * 8 + 2 * csel;
                *(float2*)(Ss + row0 * SSTRIDE + col) =
                    make_float2(accS[nt][0] * scale, accS[nt][1] * scale);
                *(float2*)(Ss + (row0 + 8) * SSTRIDE + col) =
                    make_float2(accS[nt][2] * scale, accS[nt][3] * scale);
            }
        }
        __syncthreads();

        // ---- online softmax: 4 threads per row; P stored tf32-rounded ----
        {
            const int r  = tid >> 2;
            const int qd = tid & 3;
            float* srow = Ss + r * SSTRIDE + qd * 16;
            float mold = m_s[r];
            float mx = mold;
#pragma unroll
            for (int c = 0; c < 16; c++) mx = fmaxf(mx, srow[c]);
            mx = fmaxf(mx, __shfl_xor_sync(0xFFFFFFFFu, mx, 1));
            mx = fmaxf(mx, __shfl_xor_sync(0xFFFFFFFFu, mx, 2));
            float ls = 0.f;
#pragma unroll
            for (int c = 0; c < 16; c++) {
                float p = __expf(srow[c] - mx);
                srow[c] = f2tf32f(p);
                ls += p;
            }
            ls += __shfl_xor_sync(0xFFFFFFFFu, ls, 1);
            ls += __shfl_xor_sync(0xFFFFFFFFu, ls, 2);
            if (qd == 0) {
                float alpha = __expf(mold - mx);
                m_s[r] = mx;
                l_s[r] = l_s[r] * alpha + ls;
                a_s[r] = alpha;
            }
        }
        __syncthreads();

        // ---- O += P @ V via tf32 mma (C-fragment rescale by alpha) ----
        {
            float al0 = a_s[pm0 + g];
            float al1 = a_s[pm0 + g + 8];
#pragma unroll
            for (int nt = 0; nt < 8; nt++) {
                accO[nt][0] *= al0;  accO[nt][1] *= al0;
                accO[nt][2] *= al1;  accO[nt][3] *= al1;
            }
            const float* Pr0 = Ss + (pm0 + g) * SSTRIDE;
            const float* Pr8 = Pr0 + 8 * SSTRIDE;
#pragma unroll
            for (int kk = 0; kk < 8; kk++) {
                const int k0 = kk * 8;
                float a0 = Pr0[k0 + csel];
                float a1 = Pr8[k0 + csel];
                float a2 = Pr0[k0 + csel + 4];
                float a3 = Pr8[k0 + csel + 4];
                const float* Vk0 = Vs + (k0 + csel) * VSTRIDE + pn0 + g;
                const float* Vk4 = Vk0 + 4 * VSTRIDE;
#pragma unroll
                for (int nt = 0; nt < 8; nt++) {
                    float b0 = Vk0[nt * 8];
                    float b1 = Vk4[nt * 8];
                    mma_tf32(accO[nt][0], accO[nt][1], accO[nt][2], accO[nt][3],
                             a0, a1, a2, a3, b0, b1);
                }
            }
        }
    }

    // ---- normalize + scatter to g_CTXp (permuted A layout, tf32) ----
    // ctx matrix: row R = b*2048 + d*16 + s_hi, col C = s_lo*16 + h
    {
        float inv0 = 1.f / l_s[pm0 + g];
        float inv1 = 1.f / l_s[pm0 + g + 8];
        int s0    = q0 + pm0 + g;               // s1 = s0+8 (same s_hi)
        int s_hi  = s0 >> 7;
        int s_lo0 = s0 & 127;
        int kin   = ((s_lo0 & 1) << 4) + h;     // same for s0, s1
        int p     = (kin & 3) * 8 + (kin >> 2);
        int idx   = (((p >> 2) ^ (s_hi & 7)) << 2) + (p & 3);
        size_t colb0 = (size_t)((s_lo0 * 16 + h) & ~31) + idx;
        size_t colb1 = colb0 + 128;             // s1 column block
        size_t rbase = ((size_t)b * 2048 + s_hi) * HID;
#pragma unroll
        for (int nt = 0; nt < 8; nt++) {
            int d0 = pn0 + nt * 8 + 2 * csel;
            size_t r0 = rbase + (size_t)d0 * 16 * HID;     // row for d0
            size_t r1 = r0 + (size_t)16 * HID;             // row for d0+1
            g_CTXp[r0 + colb0] = f2tf32f(accO[nt][0] * inv0);
            g_CTXp[r1 + colb0] = f2tf32f(accO[nt][1] * inv0);
            g_CTXp[r0 + colb1] = f2tf32f(accO[nt][2] * inv1);
            g_CTXp[r1 + colb1] = f2tf32f(accO[nt][3] * inv1);
        }
    }
}

// ---------------------------------------------------------------------------
// Launch
// ---------------------------------------------------------------------------
extern "C" void kernel_launch(void* const* d_in, const int* in_sizes, int n_in,
                              void* d_out, int out_size)
{
    (void)in_sizes; (void)n_in; (void)out_size;
    const float* X  = (const float*)d_in[0];
    const float* Wq = (const float*)d_in[1];
    const float* bq = (const float*)d_in[2];
    const float* Wk = (const float*)d_in[3];
    const float* bk = (const float*)d_in[4];
    const float* Wv = (const float*)d_in[5];
    const float* bv = (const float*)d_in[6];
    const float* Wo = (const float*)d_in[7];
    const float* bo = (const float*)d_in[8];
    float* out = (float*)d_out;

    cudaFuncSetAttribute(qkv_gemm_tc, cudaFuncAttributeMaxDynamicSharedMemorySize,
                         GEMM_SMEM_BYTES);
    cudaFuncSetAttribute(out_gemm_tc, cudaFuncAttributeMaxDynamicSharedMemorySize,
                         GEMM_SMEM_BYTES);
    cudaFuncSetAttribute(attn_kernel, cudaFuncAttributeMaxDynamicSharedMemorySize,
                         ATTN_SMEM_BYTES);

    // 0) convert inputs once (X -> permuted tf32, W -> tf32)
    prep_kernel<<<dim3(8192, 1, 5), 256>>>(X, Wq, Wk, Wv, Wo);

    // 1) QKV projections (Q,K permuted; V plain tf32)
    dim3 gq(HID / 128, MROWS / 128, 3);
    qkv_gemm_tc<<<gq, 256, GEMM_SMEM_BYTES>>>(bq, bk, bv);

    // 2) attention -> permuted ctx
    dim3 ga(SEQ / 64, BATCH * NHEADS);
    attn_kernel<<<ga, 256, ATTN_SMEM_BYTES>>>();

    // 3) output projection
    dim3 go(HID / 128, MROWS / 128, 1);
    out_gemm_tc<<<go, 256, GEMM_SMEM_BYTES>>>(bo, out);
}

// round 10
// speedup vs baseline: 5.9982x; 1.1700x over previous
#include <cuda_runtime.h>
#include <math.h>
#include <stdint.h>

// Problem constants
#define HID    2048
#define BATCH  2
#define SEQ    2048
#define NHEADS 16
#define HD     128
#define MROWS  (BATCH * SEQ)   // 4096

// ---------------------------------------------------------------------------
// Scratch (static __device__ arrays — no allocation anywhere)
// ---------------------------------------------------------------------------
__device__ float g_Xp [(size_t)MROWS * HID];          // X, tf32, permuted A layout
__device__ float g_Wp [(size_t)4 * HID * HID];        // Wq,Wk,Wv,Wo tf32 (orig layout)
__device__ float g_Q  [(size_t)MROWS * HID];          // Q tf32, permuted per-head
__device__ float g_K  [(size_t)MROWS * HID];          // K tf32, permuted per-head
__device__ float g_V  [(size_t)MROWS * HID];          // V tf32, plain
__device__ float g_CTXp[(size_t)MROWS * HID];         // ctx tf32, permuted A layout

// ---------------------------------------------------------------------------
// Helpers
// ---------------------------------------------------------------------------
__device__ __forceinline__ float f2tf32f(float f) {
    uint32_t r;
    asm("cvt.rna.tf32.f32 %0, %1;" : "=r"(r) : "f"(f));
    return __uint_as_float(r);
}
__device__ __forceinline__ uint32_t smem_u32(const void* p) {
    uint32_t a;
    asm("{ .reg .u64 t; cvta.to.shared.u64 t, %1; cvt.u32.u64 %0, t; }"
        : "=r"(a) : "l"(p));
    return a;
}
__device__ __forceinline__ void cp16(uint32_t dst, const void* src) {
    asm volatile("cp.async.cg.shared.global [%0], [%1], 16;"
                 :: "r"(dst), "l"(src));
}
__device__ __forceinline__ void cp_commit() {
    asm volatile("cp.async.commit_group;");
}
template <int N>
__device__ __forceinline__ void cp_wait() {
    asm volatile("cp.async.wait_group %0;" :: "n"(N));
}

__device__ __forceinline__ void mma_tf32(float& d0, float& d1, float& d2, float& d3,
                                         float a0, float a1, float a2, float a3,
                                         float b0, float b1)
{
    asm volatile(
        "mma.sync.aligned.m16n8k8.row.col.f32.tf32.tf32.f32 "
        "{%0,%1,%2,%3}, {%4,%5,%6,%7}, {%8,%9}, {%0,%1,%2,%3};"
        : "+f"(d0), "+f"(d1), "+f"(d2), "+f"(d3)
        : "r"(__float_as_uint(a0)), "r"(__float_as_uint(a1)),
          "r"(__float_as_uint(a2)), "r"(__float_as_uint(a3)),
          "r"(__float_as_uint(b0)), "r"(__float_as_uint(b1)));
}

// ---------------------------------------------------------------------------
// Prep: z=0 -> X to permuted-tf32 g_Xp ; z=1..4 -> W* to tf32 g_Wp
// ---------------------------------------------------------------------------
__global__ __launch_bounds__(256)
void prep_kernel(const float* __restrict__ X,
                 const float* __restrict__ Wq, const float* __restrict__ Wk,
                 const float* __restrict__ Wv, const float* __restrict__ Wo)
{
    const int idx = blockIdx.x * 256 + threadIdx.x;   // float4 index
    const int z = blockIdx.z;
    if (z == 0) {
        int r   = idx >> 9;
        int rem = idx & 511;
        int c   = rem >> 3;
        int j   = rem & 7;
        float4 v = *(const float4*)(X + (size_t)r * HID + c * 32 + j * 4);
        float* dst = g_Xp + (size_t)r * HID + c * 32;
        const float vv[4] = { v.x, v.y, v.z, v.w };
#pragma unroll
        for (int e = 0; e < 4; e++) {
            int p = e * 8 + j;
            dst[(((p >> 2) ^ (r & 7)) << 2) + (p & 3)] = f2tf32f(vv[e]);
        }
    } else {
        if (idx >= (HID * HID / 4)) return;
        const float* W = (z == 1) ? Wq : (z == 2) ? Wk : (z == 3) ? Wv : Wo;
        float4 v = *(const float4*)(W + (size_t)idx * 4);
        float4 t;
        t.x = f2tf32f(v.x); t.y = f2tf32f(v.y);
        t.z = f2tf32f(v.z); t.w = f2tf32f(v.w);
        *(float4*)(g_Wp + (size_t)(z - 1) * HID * HID + (size_t)idx * 4) = t;
    }
}

// ---------------------------------------------------------------------------
// tf32 mma.sync GEMM v3 (unchanged, proven): C = Aperm @ Wp + bias
// ---------------------------------------------------------------------------
#define NSTAGE   3
#define ASTG     4096
#define BSTRIDE  136
#define BSTG     (32 * BSTRIDE)
#define GEMM_SMEM_FLOATS (NSTAGE * (ASTG + BSTG))
#define GEMM_SMEM_BYTES  (GEMM_SMEM_FLOATS * 4)

__device__ __forceinline__ void tf32_gemm_body(const float* __restrict__ Ap,
                                               const float* __restrict__ Wp,
                                               const float* __restrict__ bias,
                                               float* __restrict__ C,
                                               int mode)
{
    extern __shared__ float sm[];
    float* smA = sm;
    float* smB = sm + NSTAGE * ASTG;
    const uint32_t smA_u = smem_u32(smA);
    const uint32_t smB_u = smem_u32(smB);

    const int tid   = threadIdx.x;
    const int lane  = tid & 31;
    const int wid   = tid >> 5;
    const int warpM = wid >> 2;
    const int warpN = wid & 3;
    const int csel  = lane & 3;
    const int g     = lane >> 2;

    const int m0 = blockIdx.y * 128;
    const int n0 = blockIdx.x * 128;

    const int la_r = tid >> 3;
    const int la_j = tid & 7;
    const int lb_k = tid >> 5;
    const int lb_j = tid & 31;

    const float* Abase = Ap + (size_t)m0 * HID + la_r * HID + la_j * 4;
    const float* Bbase = Wp + (size_t)lb_k * HID + n0 + lb_j * 4;
    const uint32_t dA = smA_u + (la_r * 32 + la_j * 4) * 4;
    const uint32_t dB = smB_u + (lb_k * BSTRIDE + lb_j * 4) * 4;

    auto load_chunk = [&](int c, int st) {
        const float* As = Abase + c * 32;
        const uint32_t dAs = dA + st * (ASTG * 4);
#pragma unroll
        for (int i = 0; i < 4; i++)
            cp16(dAs + i * 32 * 32 * 4, As + (size_t)i * 32 * HID);
        const float* Bs = Bbase + (size_t)(c * 32) * HID;
        const uint32_t dBs = dB + st * (BSTG * 4);
#pragma unroll
        for (int i = 0; i < 4; i++)
            cp16(dBs + i * 8 * BSTRIDE * 4, Bs + (size_t)i * 8 * HID);
        cp_commit();
    };

    float acc[4][4][4];
#pragma unroll
    for (int mt = 0; mt < 4; mt++)
#pragma unroll
        for (int nt = 0; nt < 4; nt++)
#pragma unroll
            for (int e = 0; e < 4; e++) acc[mt][nt][e] = 0.f;

    auto compute = [&](int st) {
        const float* a = smA + st * ASTG;
        const float* b = smB + st * BSTG;
#pragma unroll
        for (int half = 0; half < 2; half++) {
            const int q = 2 * csel + half;
            float4 A0[4], A8[4];
#pragma unroll
            for (int mt = 0; mt < 4; mt++) {
                int r0 = warpM * 64 + mt * 16 + g;
                int r8 = r0 + 8;
                A0[mt] = *(const float4*)(a + r0 * 32 + ((q ^ (r0 & 7)) * 4));
                A8[mt] = *(const float4*)(a + r8 * 32 + ((q ^ (r8 & 7)) * 4));
            }
            const int kb = csel + 16 * half;
#pragma unroll
            for (int nt = 0; nt < 4; nt++) {
                int n = warpN * 32 + nt * 8 + g;
                const float* bp = b + n;
                float b0 = bp[(kb + 0)  * BSTRIDE];
                float b1 = bp[(kb + 4)  * BSTRIDE];
                float b2 = bp[(kb + 8)  * BSTRIDE];
                float b3 = bp[(kb + 12) * BSTRIDE];
#pragma unroll
                for (int mt = 0; mt < 4; mt++) {
                    mma_tf32(acc[mt][nt][0], acc[mt][nt][1],
                             acc[mt][nt][2], acc[mt][nt][3],
                             A0[mt].x, A8[mt].x, A0[mt].y, A8[mt].y, b0, b1);
                    mma_tf32(acc[mt][nt][0], acc[mt][nt][1],
                             acc[mt][nt][2], acc[mt][nt][3],
                             A0[mt].z, A8[mt].z, A0[mt].w, A8[mt].w, b2, b3);
                }
            }
        }
    };

    load_chunk(0, 0);
    load_chunk(1, 1);

    const int NC = HID / 32;
    for (int c = 0; c < NC; c++) {
        if (c == NC - 1) cp_wait<0>(); else cp_wait<1>();
        __syncthreads();
        compute(c % NSTAGE);
        if (c + 2 < NC) load_chunk(c + 2, (c + 2) % NSTAGE);
    }

    if (mode == 0) {
        const int xg = g & 7;
#pragma unroll
        for (int mt = 0; mt < 4; mt++) {
            int rg0 = m0 + warpM * 64 + mt * 16 + g;
            int rg1 = rg0 + 8;
#pragma unroll
            for (int nt = 0; nt < 4; nt++) {
                int kin0 = nt * 8 + 2 * csel;
                int colb = n0 + warpN * 32;
                int p0   = (kin0 & 3) * 8 + (kin0 >> 2);
                int x    = p0 >> 2, lo = p0 & 3;
                int idx0 = ((x ^ xg) << 2) + lo;
                int idx1 = (((x + 2) ^ xg) << 2) + lo;
                float b0 = __ldg(bias + colb + kin0);
                float b1 = __ldg(bias + colb + kin0 + 1);
                C[(size_t)rg0 * HID + colb + idx0] = f2tf32f(acc[mt][nt][0] + b0);
                C[(size_t)rg0 * HID + colb + idx1] = f2tf32f(acc[mt][nt][1] + b1);
                C[(size_t)rg1 * HID + colb + idx0] = f2tf32f(acc[mt][nt][2] + b0);
                C[(size_t)rg1 * HID + colb + idx1] = f2tf32f(acc[mt][nt][3] + b1);
            }
        }
    } else {
#pragma unroll
        for (int mt = 0; mt < 4; mt++) {
            int row = m0 + warpM * 64 + mt * 16 + g;
#pragma unroll
            for (int nt = 0; nt < 4; nt++) {
                int col = n0 + warpN * 32 + nt * 8 + 2 * csel;
                float b0 = __ldg(bias + col);
                float b1 = __ldg(bias + col + 1);
                float v0 = acc[mt][nt][0] + b0, v1 = acc[mt][nt][1] + b1;
                float v2 = acc[mt][nt][2] + b0, v3 = acc[mt][nt][3] + b1;
                if (mode == 1) {
                    v0 = f2tf32f(v0); v1 = f2tf32f(v1);
                    v2 = f2tf32f(v2); v3 = f2tf32f(v3);
                }
                *(float2*)(C + (size_t)row * HID + col)       = make_float2(v0, v1);
                *(float2*)(C + (size_t)(row + 8) * HID + col) = make_float2(v2, v3);
            }
        }
    }
}

__global__ __launch_bounds__(256, 2)
void qkv_gemm_tc(const float* __restrict__ bq,
                 const float* __restrict__ bk,
                 const float* __restrict__ bv)
{
    const float* Wz; const float* b; float* Cp; int mode;
    if (blockIdx.z == 0)      { Wz = g_Wp;                     b = bq; Cp = g_Q; mode = 0; }
    else if (blockIdx.z == 1) { Wz = g_Wp + (size_t)HID*HID;   b = bk; Cp = g_K; mode = 0; }
    else                      { Wz = g_Wp + (size_t)2*HID*HID; b = bv; Cp = g_V; mode = 1; }
    tf32_gemm_body(g_Xp, Wz, b, Cp, mode);
}

__global__ __launch_bounds__(256, 2)
void out_gemm_tc(const float* __restrict__ bo, float* __restrict__ out)
{
    tf32_gemm_body(g_CTXp, g_Wp + (size_t)3 * HID * HID, bo, out, 2);
}

// ---------------------------------------------------------------------------
// Attention v5: BM=128 (one CTA = 128 q rows), 8 warps each owning a 16-row
// slab (full 64 key cols for S, full 128 d cols for O).
// K single-buffered but reloaded DURING softmax+PV (Ks dead after S phase);
// V double-buffered. All tensor work tf32 mma. Output -> g_CTXp (permuted).
// ---------------------------------------------------------------------------
#define SSTRIDE 68
#define VSTRIDE 136
#define VBUF    (64 * VSTRIDE)               // 8704 floats per V stage
// floats: Qs 16384 | Ks 8192 | Vs 2x8704 | Ss 128x68=8704 | m/l/a 384
#define ATTN_SMEM_FLOATS (16384 + 8192 + 2 * VBUF + 128 * SSTRIDE + 384)
#define ATTN_SMEM_BYTES  (ATTN_SMEM_FLOATS * 4)

__global__ __launch_bounds__(256)
void attn_kernel()
{
    extern __shared__ float smf[];
    float* Qs  = smf;                    // 4 chunks x 128 x 32 (permuted tf32)
    float* Ks  = Qs + 16384;             // 4 chunks x 64 x 32
    float* Vs  = Ks + 8192;              // 2 x (64 x VSTRIDE)
    float* Ss  = Vs + 2 * VBUF;          // 128 x SSTRIDE
    float* m_s = Ss + 128 * SSTRIDE;     // 128
    float* l_s = m_s + 128;
    float* a_s = l_s + 128;
    const uint32_t Qs_u = smem_u32(Qs);
    const uint32_t Ks_u = smem_u32(Ks);
    const uint32_t Vs_u = smem_u32(Vs);

    const int tid  = threadIdx.x;
    const int lane = tid & 31;
    const int wid  = tid >> 5;           // warp owns rows [wid*16, wid*16+16)
    const int csel = lane & 3;
    const int g    = lane >> 2;

    const int bh  = blockIdx.y;
    const int b   = bh >> 4;
    const int h   = bh & 15;
    const int q0  = blockIdx.x * 128;
    const size_t rowbase = (size_t)b * SEQ;
    const float scale = 0.08838834764831845f;   // 1/sqrt(128)

    const int pm0 = wid * 16;

    // ---- Q tile: 128 rows x 128 d -> permuted layout (16 iters) ----
    {
        const float* Qg = g_Q + (rowbase + q0) * HID + h * HD;
#pragma unroll
        for (int it = 0; it < 16; it++) {
            int idx = tid + it * 256;
            int r   = idx >> 5;
            int rem = idx & 31;
            cp16(Qs_u + (((rem >> 3) * 4096 + r * 32 + (rem & 7) * 4) * 4),
                 Qg + (size_t)r * HID + rem * 4);
        }
    }
    // ---- preload K/V tile 0 ----
    {
        const float* Kg = g_K + rowbase * HID + h * HD;
        const float* Vg = g_V + rowbase * HID + h * HD;
#pragma unroll
        for (int it = 0; it < 8; it++) {
            int idx = tid + it * 256;
            int r   = idx >> 5;
            int rem = idx & 31;
            cp16(Ks_u + (((rem >> 3) * 2048 + r * 32 + (rem & 7) * 4) * 4),
                 Kg + (size_t)r * HID + rem * 4);
            cp16(Vs_u + ((r * VSTRIDE + rem * 4) * 4),
                 Vg + (size_t)r * HID + rem * 4);
        }
        cp_commit();
    }
    if (tid < 128) { m_s[tid] = -INFINITY; l_s[tid] = 0.f; }

    float accO[16][4];
#pragma unroll
    for (int nt = 0; nt < 16; nt++)
#pragma unroll
        for (int e = 0; e < 4; e++) accO[nt][e] = 0.f;

    const int NT = SEQ / 64;   // 32
    for (int jt = 0; jt < NT; jt++) {
        cp_wait<0>();
        __syncthreads();       // loads ready; prior-iter readers of Ss/Vs done

        // ---- S = (Q K^T): warp tile 16 x 64 ----
        {
            float accS[8][4];
#pragma unroll
            for (int nt = 0; nt < 8; nt++)
#pragma unroll
                for (int e = 0; e < 4; e++) accS[nt][e] = 0.f;

#pragma unroll
            for (int ch = 0; ch < 4; ch++) {
                const float* qa = Qs + ch * 4096;
                const float* kb = Ks + ch * 2048;
#pragma unroll
                for (int half = 0; half < 2; half++) {
                    const int q = 2 * csel + half;
                    int r0 = pm0 + g;
                    int r8 = r0 + 8;
                    float4 A0 = *(const float4*)(qa + r0 * 32 + ((q ^ (r0 & 7)) * 4));
                    float4 A8 = *(const float4*)(qa + r8 * 32 + ((q ^ (r8 & 7)) * 4));
#pragma unroll
                    for (int nt = 0; nt < 8; nt++) {
                        int n = nt * 8 + g;
                        float4 Bf = *(const float4*)(kb + n * 32 + ((q ^ (n & 7)) * 4));
                        mma_tf32(accS[nt][0], accS[nt][1], accS[nt][2], accS[nt][3],
                                 A0.x, A8.x, A0.y, A8.y, Bf.x, Bf.y);
                        mma_tf32(accS[nt][0], accS[nt][1], accS[nt][2], accS[nt][3],
                                 A0.z, A8.z, A0.w, A8.w, Bf.z, Bf.w);
                    }
                }
            }
            int row0 = pm0 + g;
#pragma unroll
            for (int nt = 0; nt < 8; nt++) {
                int col = nt * 8 + 2 * csel;
                *(float2*)(Ss + row0 * SSTRIDE + col) =
                    make_float2(accS[nt][0] * scale, accS[nt][1] * scale);
                *(float2*)(Ss + (row0 + 8) * SSTRIDE + col) =
                    make_float2(accS[nt][2] * scale, accS[nt][3] * scale);
            }
        }
        __syncthreads();       // Ks fully consumed; Ss written

        // ---- prefetch K/V for jt+1 (overlaps softmax + PV) ----
        if (jt + 1 < NT) {
            const float* Kg = g_K + (rowbase + (jt + 1) * 64) * HID + h * HD;
            const float* Vg = g_V + (rowbase + (jt + 1) * 64) * HID + h * HD;
            const uint32_t vb = ((jt + 1) & 1) * (VBUF * 4);
#pragma unroll
            for (int it = 0; it < 8; it++) {
                int idx = tid + it * 256;
                int r   = idx >> 5;
                int rem = idx & 31;
                cp16(Ks_u + (((rem >> 3) * 2048 + r * 32 + (rem & 7) * 4) * 4),
                     Kg + (size_t)r * HID + rem * 4);
                cp16(Vs_u + vb + ((r * VSTRIDE + rem * 4) * 4),
                     Vg + (size_t)r * HID + rem * 4);
            }
            cp_commit();
        }

        // ---- online softmax: 2 threads per row (32 cols each) ----
        {
            const int r  = tid >> 1;
            const int qd = tid & 1;
            float* srow = Ss + r * SSTRIDE + qd * 32;
            float mold = m_s[r];
            float mx = mold;
#pragma unroll
            for (int c = 0; c < 32; c++) mx = fmaxf(mx, srow[c]);
            mx = fmaxf(mx, __shfl_xor_sync(0xFFFFFFFFu, mx, 1));
            float ls = 0.f;
#pragma unroll
            for (int c = 0; c < 32; c++) {
                float p = __expf(srow[c] - mx);
                srow[c] = f2tf32f(p);
                ls += p;
            }
            ls += __shfl_xor_sync(0xFFFFFFFFu, ls, 1);
            if (qd == 0) {
                float alpha = __expf(mold - mx);
                m_s[r] = mx;
                l_s[r] = l_s[r] * alpha + ls;
                a_s[r] = alpha;
            }
        }
        __syncthreads();

        // ---- O += P @ V : warp tile 16 x 128 ----
        {
            const float* Vb = Vs + (jt & 1) * VBUF;
            float al0 = a_s[pm0 + g];
            float al1 = a_s[pm0 + g + 8];
#pragma unroll
            for (int nt = 0; nt < 16; nt++) {
                accO[nt][0] *= al0;  accO[nt][1] *= al0;
                accO[nt][2] *= al1;  accO[nt][3] *= al1;
            }
            const float* Pr0 = Ss + (pm0 + g) * SSTRIDE;
            const float* Pr8 = Pr0 + 8 * SSTRIDE;
#pragma unroll
            for (int kk = 0; kk < 8; kk++) {
                const int k0 = kk * 8;
                float a0 = Pr0[k0 + csel];
                float a1 = Pr8[k0 + csel];
                float a2 = Pr0[k0 + csel + 4];
                float a3 = Pr8[k0 + csel + 4];
                const float* Vk0 = Vb + (k0 + csel) * VSTRIDE + g;
                const float* Vk4 = Vk0 + 4 * VSTRIDE;
#pragma unroll
                for (int nt = 0; nt < 16; nt++) {
                    float b0 = Vk0[nt * 8];
                    float b1 = Vk4[nt * 8];
                    mma_tf32(accO[nt][0], accO[nt][1], accO[nt][2], accO[nt][3],
                             a0, a1, a2, a3, b0, b1);
                }
            }
        }
    }

    // ---- normalize + scatter to g_CTXp (permuted A layout, tf32) ----
    {
        float inv0 = 1.f / l_s[pm0 + g];
        float inv1 = 1.f / l_s[pm0 + g + 8];
        int s0    = q0 + pm0 + g;               // s1 = s0+8 (same s_hi)
        int s_hi  = s0 >> 7;
        int s_lo0 = s0 & 127;
        int kin   = ((s_lo0 & 1) << 4) + h;
        int p     = (kin & 3) * 8 + (kin >> 2);
        int idx   = (((p >> 2) ^ (s_hi & 7)) << 2) + (p & 3);
        size_t colb0 = (size_t)((s_lo0 * 16 + h) & ~31) + idx;
        size_t colb1 = colb0 + 128;
        size_t rbase = ((size_t)b * 2048 + s_hi) * HID;
#pragma unroll
        for (int nt = 0; nt < 16; nt++) {
            int d0 = nt * 8 + 2 * csel;
            size_t r0 = rbase + (size_t)d0 * 16 * HID;
            size_t r1 = r0 + (size_t)16 * HID;
            g_CTXp[r0 + colb0] = f2tf32f(accO[nt][0] * inv0);
            g_CTXp[r1 + colb0] = f2tf32f(accO[nt][1] * inv0);
            g_CTXp[r0 + colb1] = f2tf32f(accO[nt][2] * inv1);
            g_CTXp[r1 + colb1] = f2tf32f(accO[nt][3] * inv1);
        }
    }
}

// ---------------------------------------------------------------------------
// Launch
// ---------------------------------------------------------------------------
extern "C" void kernel_launch(void* const* d_in, const int* in_sizes, int n_in,
                              void* d_out, int out_size)
{
    (void)in_sizes; (void)n_in; (void)out_size;
    const float* X  = (const float*)d_in[0];
    const float* Wq = (const float*)d_in[1];
    const float* bq = (const float*)d_in[2];
    const float* Wk = (const float*)d_in[3];
    const float* bk = (const float*)d_in[4];
    const float* Wv = (const float*)d_in[5];
    const float* bv = (const float*)d_in[6];
    const float* Wo = (const float*)d_in[7];
    const float* bo = (const float*)d_in[8];
    float* out = (float*)d_out;

    cudaFuncSetAttribute(qkv_gemm_tc, cudaFuncAttributeMaxDynamicSharedMemorySize,
                         GEMM_SMEM_BYTES);
    cudaFuncSetAttribute(out_gemm_tc, cudaFuncAttributeMaxDynamicSharedMemorySize,
                         GEMM_SMEM_BYTES);
    cudaFuncSetAttribute(attn_kernel, cudaFuncAttributeMaxDynamicSharedMemorySize,
                         ATTN_SMEM_BYTES);

    // 0) convert inputs once (X -> permuted tf32, W -> tf32)
    prep_kernel<<<dim3(8192, 1, 5), 256>>>(X, Wq, Wk, Wv, Wo);

    // 1) QKV projections (Q,K permuted; V plain tf32)
    dim3 gq(HID / 128, MROWS / 128, 3);
    qkv_gemm_tc<<<gq, 256, GEMM_SMEM_BYTES>>>(bq, bk, bv);

    // 2) attention (BM=128) -> permuted ctx
    dim3 ga(SEQ / 128, BATCH * NHEADS);
    attn_kernel<<<ga, 256, ATTN_SMEM_BYTES>>>();

    // 3) output projection
    dim3 go(HID / 128, MROWS / 128, 1);
    out_gemm_tc<<<go, 256, GEMM_SMEM_BYTES>>>(bo, out);
}